// round 2
// baseline (speedup 1.0000x reference)
#include <cuda_runtime.h>
#include <math.h>

// Problem constants (fixed by the dataset)
#define BATCH 8
#define HEADS 8
#define SEQ   2048
#define DH    64

#define BM 64              // query tile
#define BN 64              // key tile
#define NTILES (SEQ / BN)

#define QS_STRIDE 68       // padded strides (floats) to dodge bank conflicts
#define KT_STRIDE 68
#define PS_STRIDE 68
#define VS_STRIDE 64

#define SMEM_FLOATS (BM*QS_STRIDE + DH*KT_STRIDE + BM*PS_STRIDE + BN*VS_STRIDE)
#define SMEM_BYTES  (SMEM_FLOATS * 4)

__global__ void __launch_bounds__(256)
attn_fp32_kernel(const float* __restrict__ Qg_,
                 const float* __restrict__ Kg_,
                 const float* __restrict__ Vg_,
                 const int* __restrict__ maskg,   // bool canonicalized to int32 by harness
                 float* __restrict__ Og_)
{
    extern __shared__ float sm[];
    float* Qs = sm;                              // [BM][QS_STRIDE]
    float* Kt = Qs + BM * QS_STRIDE;             // [DH][KT_STRIDE]  (d-major: Kt[d][key])
    float* Ps = Kt + DH * KT_STRIDE;             // [BM][PS_STRIDE]
    float* Vs = Ps + BM * PS_STRIDE;             // [BN][VS_STRIDE]
    __shared__ int msk[BN];

    const int tid = threadIdx.x;
    const int tx  = tid & 15;        // 16 threads across key/d columns
    const int ty  = tid >> 4;        // 16 thread rows, 4 query rows each
    const int bh  = blockIdx.y;
    const int b   = bh >> 3;         // H = 8
    const int q0  = blockIdx.x * BM;

    const float* Qg = Qg_ + ((size_t)bh * SEQ + q0) * DH;
    const float* Kg = Kg_ + (size_t)bh * SEQ * DH;
    const float* Vg = Vg_ + (size_t)bh * SEQ * DH;
    const int* mg = maskg + (size_t)b * SEQ;
    float* Og = Og_ + ((size_t)bh * SEQ + q0) * DH;

    // ---- Load Q tile (64x64) into smem, coalesced float4 ----
    #pragma unroll
    for (int it = 0; it < 4; it++) {
        int idx = tid + it * 256;            // [0,1024)
        int r   = idx >> 4;
        int c4  = (idx & 15) << 2;
        float4 v = *(const float4*)(Qg + r * DH + c4);
        *(float4*)(Qs + r * QS_STRIDE + c4) = v;
    }

    float o[4][4];
    #pragma unroll
    for (int i = 0; i < 4; i++)
        #pragma unroll
        for (int j = 0; j < 4; j++) o[i][j] = 0.f;
    float mrow[4] = {-INFINITY, -INFINITY, -INFINITY, -INFINITY};
    float lrow[4] = {0.f, 0.f, 0.f, 0.f};

    for (int kt = 0; kt < NTILES; kt++) {
        const int k0 = kt * BN;
        __syncthreads();   // previous PV reads of Kt/Vs/Ps done

        // ---- Load K tile transposed: Kt[d][key] ----
        #pragma unroll
        for (int it = 0; it < 4; it++) {
            int idx = tid + it * 256;
            int key = idx >> 4;
            int c4  = (idx & 15) << 2;
            float4 v = *(const float4*)(Kg + (size_t)(k0 + key) * DH + c4);
            Kt[(c4 + 0) * KT_STRIDE + key] = v.x;
            Kt[(c4 + 1) * KT_STRIDE + key] = v.y;
            Kt[(c4 + 2) * KT_STRIDE + key] = v.z;
            Kt[(c4 + 3) * KT_STRIDE + key] = v.w;
        }
        // ---- Load V tile (natural layout) ----
        #pragma unroll
        for (int it = 0; it < 4; it++) {
            int idx = tid + it * 256;
            int r   = idx >> 4;
            int c4  = (idx & 15) << 2;
            *(float4*)(Vs + r * VS_STRIDE + c4) =
                *(const float4*)(Vg + (size_t)(k0 + r) * DH + c4);
        }
        if (tid < BN) msk[tid] = mg[k0 + tid];
        __syncthreads();

        // ---- S = Q K^T, 4x4 microtile per thread ----
        float s[4][4];
        #pragma unroll
        for (int i = 0; i < 4; i++)
            #pragma unroll
            for (int j = 0; j < 4; j++) s[i][j] = 0.f;

        #pragma unroll
        for (int d4 = 0; d4 < DH; d4 += 4) {
            float4 qv[4], kv[4];
            #pragma unroll
            for (int i = 0; i < 4; i++)
                qv[i] = *(const float4*)(Qs + (ty * 4 + i) * QS_STRIDE + d4);
            #pragma unroll
            for (int t = 0; t < 4; t++)
                kv[t] = *(const float4*)(Kt + (d4 + t) * KT_STRIDE + tx * 4);
            const float* qf = reinterpret_cast<const float*>(qv);
            const float* kf = reinterpret_cast<const float*>(kv);
            #pragma unroll
            for (int i = 0; i < 4; i++)
                #pragma unroll
                for (int t = 0; t < 4; t++) {
                    float qq = qf[i * 4 + t];
                    #pragma unroll
                    for (int j = 0; j < 4; j++)
                        s[i][j] += qq * kf[t * 4 + j];
                }
        }

        // ---- logits = 10*tanh(s/8), mask -> -1e10 ----
        #pragma unroll
        for (int i = 0; i < 4; i++)
            #pragma unroll
            for (int j = 0; j < 4; j++) {
                float x  = s[i][j] * 0.125f;
                float ax = fabsf(x);
                float e  = __expf(-2.f * ax);
                float t  = __fdividef(1.f - e, 1.f + e);
                float lg = copysignf(t, x) * 10.f;
                s[i][j] = msk[tx * 4 + j] ? -1e10f : lg;
            }

        // ---- online softmax ----
        float nm[4], corr[4];
        #pragma unroll
        for (int i = 0; i < 4; i++) {
            float rm = fmaxf(fmaxf(s[i][0], s[i][1]), fmaxf(s[i][2], s[i][3]));
            #pragma unroll
            for (int off = 8; off >= 1; off >>= 1)
                rm = fmaxf(rm, __shfl_xor_sync(0xffffffffu, rm, off));
            nm[i]   = fmaxf(mrow[i], rm);
            corr[i] = __expf(mrow[i] - nm[i]);
            mrow[i] = nm[i];
        }
        #pragma unroll
        for (int i = 0; i < 4; i++) {
            float rs = 0.f;
            #pragma unroll
            for (int j = 0; j < 4; j++) {
                s[i][j] = __expf(s[i][j] - nm[i]);
                rs += s[i][j];
            }
            #pragma unroll
            for (int off = 8; off >= 1; off >>= 1)
                rs += __shfl_xor_sync(0xffffffffu, rs, off);
            lrow[i] = lrow[i] * corr[i] + rs;
            #pragma unroll
            for (int j = 0; j < 4; j++) o[i][j] *= corr[i];
            *(float4*)(Ps + (ty * 4 + i) * PS_STRIDE + tx * 4) =
                make_float4(s[i][0], s[i][1], s[i][2], s[i][3]);
        }
        __syncthreads();

        // ---- O += P V, 4x4 microtile ----
        #pragma unroll
        for (int k4 = 0; k4 < BN; k4 += 4) {
            float4 pv[4], vv[4];
            #pragma unroll
            for (int i = 0; i < 4; i++)
                pv[i] = *(const float4*)(Ps + (ty * 4 + i) * PS_STRIDE + k4);
            #pragma unroll
            for (int t = 0; t < 4; t++)
                vv[t] = *(const float4*)(Vs + (k4 + t) * VS_STRIDE + tx * 4);
            const float* pf = reinterpret_cast<const float*>(pv);
            const float* vf = reinterpret_cast<const float*>(vv);
            #pragma unroll
            for (int i = 0; i < 4; i++)
                #pragma unroll
                for (int t = 0; t < 4; t++) {
                    float pp = pf[i * 4 + t];
                    #pragma unroll
                    for (int j = 0; j < 4; j++)
                        o[i][j] += pp * vf[t * 4 + j];
                }
        }
    }

    // ---- epilogue: normalize and store ----
    #pragma unroll
    for (int i = 0; i < 4; i++) {
        float inv = __fdividef(1.f, lrow[i]);
        float4 r = make_float4(o[i][0] * inv, o[i][1] * inv,
                               o[i][2] * inv, o[i][3] * inv);
        *(float4*)(Og + (size_t)(ty * 4 + i) * DH + tx * 4) = r;
    }
}

extern "C" void kernel_launch(void* const* d_in, const int* in_sizes, int n_in,
                              void* d_out, int out_size)
{
    const float* Q = (const float*)d_in[0];
    const float* K = (const float*)d_in[1];
    const float* V = (const float*)d_in[2];
    const int* mask = (const int*)d_in[3];
    float* out = (float*)d_out;

    // Idempotent, deterministic, capture-safe (not a stream op, not an alloc).
    cudaFuncSetAttribute(attn_fp32_kernel,
                         cudaFuncAttributeMaxDynamicSharedMemorySize, SMEM_BYTES);

    dim3 grid(SEQ / BM, BATCH * HEADS);
    attn_fp32_kernel<<<grid, 256, SMEM_BYTES>>>(Q, K, V, mask, out);
}

// round 4
// speedup vs baseline: 1.6516x; 1.6516x over previous
#include <cuda_runtime.h>
#include <cstdint>
#include <math.h>

#define BATCH 8
#define HEADS 8
#define SEQ   2048
#define DH    64
#define BM    64
#define BN    64
#define NTILES (SEQ / BN)
#define STR   68          // smem row stride in floats (68 % 32 == 4 -> conflict-free patterns)

// smem layout (floats): KH[64*68] | KL[64*68] | VS[64*68] | PS[4][16*68] | MSK[64 ints]
#define OFF_KH 0
#define OFF_KL (64 * STR)
#define OFF_VS (128 * STR)
#define OFF_PS (192 * STR)
#define OFF_MSK (OFF_PS + 4 * 16 * STR)
#define SMEM_FLOATS (OFF_MSK + 64)
#define SMEM_BYTES  (SMEM_FLOATS * 4)

__device__ __forceinline__ uint32_t f2tf(float x) {
    uint32_t r; asm("cvt.rna.tf32.f32 %0, %1;" : "=r"(r) : "f"(x)); return r;
}
__device__ __forceinline__ float ex2f(float x) {
    float r; asm("ex2.approx.f32 %0, %1;" : "=f"(r) : "f"(x)); return r;
}
__device__ __forceinline__ float rcpf(float x) {
    float r; asm("rcp.approx.f32 %0, %1;" : "=f"(r) : "f"(x)); return r;
}
__device__ __forceinline__ void mma8(float* d, const uint32_t* a, uint32_t b0, uint32_t b1) {
    asm volatile(
        "mma.sync.aligned.m16n8k8.row.col.f32.tf32.tf32.f32 "
        "{%0,%1,%2,%3}, {%4,%5,%6,%7}, {%8,%9}, {%0,%1,%2,%3};"
        : "+f"(d[0]), "+f"(d[1]), "+f"(d[2]), "+f"(d[3])
        : "r"(a[0]), "r"(a[1]), "r"(a[2]), "r"(a[3]), "r"(b0), "r"(b1));
}

__global__ void __launch_bounds__(128, 3)
attn_mma_kernel(const float* __restrict__ Qg_, const float* __restrict__ Kg_,
                const float* __restrict__ Vg_, const int* __restrict__ maskg,
                float* __restrict__ Og_)
{
    extern __shared__ float sm[];
    float* KH = sm + OFF_KH;
    float* KL = sm + OFF_KL;
    float* VS = sm + OFF_VS;
    int*   MSK = (int*)(sm + OFF_MSK);

    const int tid  = threadIdx.x;
    const int wid  = tid >> 5;
    const int lane = tid & 31;
    const int r    = lane >> 2;   // groupID (row within 8)
    const int c    = lane & 3;    // threadID_in_group

    float* PS = sm + OFF_PS + wid * (16 * STR);

    const int bh = blockIdx.y;
    const int b  = bh >> 3;
    const int q0 = blockIdx.x * BM;

    const float* Qg = Qg_ + ((size_t)bh * SEQ + q0 + wid * 16) * DH;
    const float* Kg = Kg_ + (size_t)bh * SEQ * DH;
    const float* Vg = Vg_ + (size_t)bh * SEQ * DH;
    const int*   mg = maskg + (size_t)b * SEQ;
    float* Og = Og_ + ((size_t)bh * SEQ + q0 + wid * 16) * DH;

    // ---- Q fragments (persistent): a0=(r,c) a1=(r+8,c) a2=(r,c+4) a3=(r+8,c+4) ----
    uint32_t qh[8][4], ql[8][4];
    #pragma unroll
    for (int kt = 0; kt < 8; kt++) {
        #pragma unroll
        for (int j = 0; j < 4; j++) {
            int row = r + (j & 1) * 8;
            int col = kt * 8 + c + (j >> 1) * 4;
            float v = Qg[row * DH + col];
            uint32_t h = f2tf(v);
            qh[kt][j] = h;
            ql[kt][j] = f2tf(v - __uint_as_float(h));
        }
    }

    float o[8][4];
    #pragma unroll
    for (int nt = 0; nt < 8; nt++)
        #pragma unroll
        for (int j = 0; j < 4; j++) o[nt][j] = 0.f;
    float lsum0 = 0.f, lsum1 = 0.f;

    for (int t = 0; t < NTILES; t++) {
        const int k0 = t * BN;
        __syncthreads();   // everyone done reading smem of previous tile

        // ---- fill K hi/lo + V (natural [key][d], stride 68) ----
        #pragma unroll
        for (int it = 0; it < 8; it++) {
            int idx = tid + it * 128;
            int key = idx >> 4;
            int c4  = (idx & 15) << 2;
            float4 kv = *(const float4*)(Kg + (size_t)(k0 + key) * DH + c4);
            uint32_t h0 = f2tf(kv.x), h1 = f2tf(kv.y), h2 = f2tf(kv.z), h3 = f2tf(kv.w);
            *(uint4*)(KH + key * STR + c4) = make_uint4(h0, h1, h2, h3);
            *(uint4*)(KL + key * STR + c4) = make_uint4(
                f2tf(kv.x - __uint_as_float(h0)), f2tf(kv.y - __uint_as_float(h1)),
                f2tf(kv.z - __uint_as_float(h2)), f2tf(kv.w - __uint_as_float(h3)));
            float4 vv = *(const float4*)(Vg + (size_t)(k0 + key) * DH + c4);
            *(uint4*)(VS + key * STR + c4) = make_uint4(f2tf(vv.x), f2tf(vv.y),
                                                        f2tf(vv.z), f2tf(vv.w));
        }
        if (tid < BN) MSK[tid] = mg[k0 + tid];
        __syncthreads();

        // ---- S = Qh*Kh + Qh*Kl + Ql*Kh ; B[k=d][n=key] = K[key][d] ----
        float s[8][4];
        #pragma unroll
        for (int nt = 0; nt < 8; nt++)
            #pragma unroll
            for (int j = 0; j < 4; j++) s[nt][j] = 0.f;

        #pragma unroll
        for (int kt = 0; kt < 8; kt++) {
            #pragma unroll
            for (int nt = 0; nt < 8; nt++) {
                const float* kb = KH + (nt * 8 + r) * STR + kt * 8 + c;
                uint32_t bh0 = __float_as_uint(kb[0]);
                uint32_t bh1 = __float_as_uint(kb[4]);
                const float* lb = KL + (nt * 8 + r) * STR + kt * 8 + c;
                uint32_t bl0 = __float_as_uint(lb[0]);
                uint32_t bl1 = __float_as_uint(lb[4]);
                mma8(s[nt], qh[kt], bh0, bh1);
                mma8(s[nt], qh[kt], bl0, bl1);
                mma8(s[nt], ql[kt], bh0, bh1);
            }
        }

        // ---- softmax: p = exp2(14.4269504*(tanh(s/8)-1)), masked -> 0 ----
        #pragma unroll
        for (int nt = 0; nt < 8; nt++) {
            int m0 = MSK[nt * 8 + 2 * c];
            int m1 = MSK[nt * 8 + 2 * c + 1];
            float p[4];
            #pragma unroll
            for (int j = 0; j < 4; j++) {
                float sv = s[nt][j];
                float ax = fabsf(sv) * 0.125f;
                float e2 = ex2f(ax * -2.8853900817779268f);   // e^{-2|x|}
                float tt = 1.f - 2.f * e2 * rcpf(1.f + e2);   // tanh(|x|)
                float ts = copysignf(tt, sv);
                float pv = ex2f(14.4269504088896f * (ts - 1.f));
                pv = ((j & 1) ? m1 : m0) ? 0.f : pv;
                p[j] = __uint_as_float(f2tf(pv));             // tf32-rounded, used everywhere
            }
            lsum0 += p[0] + p[1];
            lsum1 += p[2] + p[3];
            *(float2*)(PS + r * STR + nt * 8 + 2 * c)       = make_float2(p[0], p[1]);
            *(float2*)(PS + (r + 8) * STR + nt * 8 + 2 * c) = make_float2(p[2], p[3]);
        }
        __syncwarp();

        // ---- O += P * V ; A = P (m16k8), B[k=key][n=d] = V[key][d] ----
        #pragma unroll
        for (int kt = 0; kt < 8; kt++) {
            uint32_t a[4];
            a[0] = __float_as_uint(PS[r * STR + kt * 8 + c]);
            a[1] = __float_as_uint(PS[(r + 8) * STR + kt * 8 + c]);
            a[2] = __float_as_uint(PS[r * STR + kt * 8 + c + 4]);
            a[3] = __float_as_uint(PS[(r + 8) * STR + kt * 8 + c + 4]);
            #pragma unroll
            for (int nt = 0; nt < 8; nt++) {
                uint32_t b0 = __float_as_uint(VS[(kt * 8 + c) * STR + nt * 8 + r]);
                uint32_t b1 = __float_as_uint(VS[(kt * 8 + c + 4) * STR + nt * 8 + r]);
                mma8(o[nt], a, b0, b1);
            }
        }
    }

    // ---- row sums across the 4-lane quad, then normalize + store ----
    lsum0 += __shfl_xor_sync(0xffffffffu, lsum0, 1);
    lsum0 += __shfl_xor_sync(0xffffffffu, lsum0, 2);
    lsum1 += __shfl_xor_sync(0xffffffffu, lsum1, 1);
    lsum1 += __shfl_xor_sync(0xffffffffu, lsum1, 2);
    float inv0 = rcpf(lsum0);
    float inv1 = rcpf(lsum1);
    #pragma unroll
    for (int nt = 0; nt < 8; nt++) {
        int col = nt * 8 + 2 * c;
        *(float2*)(Og + r * DH + col)       = make_float2(o[nt][0] * inv0, o[nt][1] * inv0);
        *(float2*)(Og + (r + 8) * DH + col) = make_float2(o[nt][2] * inv1, o[nt][3] * inv1);
    }
}

extern "C" void kernel_launch(void* const* d_in, const int* in_sizes, int n_in,
                              void* d_out, int out_size)
{
    const float* Q = (const float*)d_in[0];
    const float* K = (const float*)d_in[1];
    const float* V = (const float*)d_in[2];
    const int* mask = (const int*)d_in[3];
    float* out = (float*)d_out;

    cudaFuncSetAttribute(attn_mma_kernel,
                         cudaFuncAttributeMaxDynamicSharedMemorySize, SMEM_BYTES);

    dim3 grid(SEQ / BM, BATCH * HEADS);
    attn_mma_kernel<<<grid, 128, SMEM_BYTES>>>(Q, K, V, mask, out);
}

// round 5
// speedup vs baseline: 2.6758x; 1.6202x over previous
#include <cuda_runtime.h>
#include <cstdint>
#include <math.h>

#define BATCH 8
#define HEADS 8
#define SEQ   2048
#define DH    64
#define BM    64
#define BN    64
#define NTILES (SEQ / BN)

// ---- smem layout in 32-bit words ----
// VS double buffer (f32, stride 68), KH/KL (bf16 rows, 36 words = 72 bf16),
// PS per-warp (f32 stride 68), MSK double buffer.
#define VSTR   68
#define KSTRW  36
#define W_VS0  0
#define W_VS1  (64 * VSTR)
#define W_KH   (2 * 64 * VSTR)
#define W_KL   (W_KH + 64 * KSTRW)
#define W_PS   (W_KL + 64 * KSTRW)
#define W_MSK  (W_PS + 4 * 16 * VSTR)
#define SMEM_WORDS (W_MSK + 128)
#define SMEM_BYTES (SMEM_WORDS * 4)

__device__ __forceinline__ uint32_t smem_u32(const void* p) {
    uint32_t a;
    asm("{ .reg .u64 t; cvta.to.shared.u64 t, %1; cvt.u32.u64 %0, t; }" : "=r"(a) : "l"(p));
    return a;
}
__device__ __forceinline__ uint32_t f2tf(float x) {
    uint32_t r; asm("cvt.rna.tf32.f32 %0, %1;" : "=r"(r) : "f"(x)); return r;
}
__device__ __forceinline__ float ex2f(float x) {
    float r; asm("ex2.approx.f32 %0, %1;" : "=f"(r) : "f"(x)); return r;
}
__device__ __forceinline__ float rcpf(float x) {
    float r; asm("rcp.approx.f32 %0, %1;" : "=f"(r) : "f"(x)); return r;
}
// pack two f32 -> bf16x2; first operand lands in HIGH half (PTX cvt d,a,b: d.hi=a)
__device__ __forceinline__ uint32_t bfpk(float hi, float lo) {
    uint32_t r; asm("cvt.rn.bf16x2.f32 %0, %1, %2;" : "=r"(r) : "f"(hi), "f"(lo)); return r;
}
__device__ __forceinline__ float bflo_f(uint32_t p) { return __uint_as_float(p << 16); }
__device__ __forceinline__ float bfhi_f(uint32_t p) { return __uint_as_float(p & 0xFFFF0000u); }

__device__ __forceinline__ void mma_bf16(float* d, const uint32_t* a, uint32_t b0, uint32_t b1) {
    asm volatile(
        "mma.sync.aligned.m16n8k16.row.col.f32.bf16.bf16.f32 "
        "{%0,%1,%2,%3}, {%4,%5,%6,%7}, {%8,%9}, {%0,%1,%2,%3};"
        : "+f"(d[0]), "+f"(d[1]), "+f"(d[2]), "+f"(d[3])
        : "r"(a[0]), "r"(a[1]), "r"(a[2]), "r"(a[3]), "r"(b0), "r"(b1));
}
__device__ __forceinline__ void mma_tf32(float* d, const uint32_t* a, uint32_t b0, uint32_t b1) {
    asm volatile(
        "mma.sync.aligned.m16n8k8.row.col.f32.tf32.tf32.f32 "
        "{%0,%1,%2,%3}, {%4,%5,%6,%7}, {%8,%9}, {%0,%1,%2,%3};"
        : "+f"(d[0]), "+f"(d[1]), "+f"(d[2]), "+f"(d[3])
        : "r"(a[0]), "r"(a[1]), "r"(a[2]), "r"(a[3]), "r"(b0), "r"(b1));
}
__device__ __forceinline__ void cpa16(uint32_t dst, const void* src) {
    asm volatile("cp.async.cg.shared.global [%0], [%1], 16;" :: "r"(dst), "l"(src));
}
__device__ __forceinline__ void cpa4(uint32_t dst, const void* src) {
    asm volatile("cp.async.ca.shared.global [%0], [%1], 4;" :: "r"(dst), "l"(src));
}
#define CP_COMMIT() asm volatile("cp.async.commit_group;" ::: "memory")
#define CP_WAIT0()  asm volatile("cp.async.wait_group 0;" ::: "memory")

__global__ void __launch_bounds__(128, 3)
attn_mma_kernel(const float* __restrict__ Qg_, const float* __restrict__ Kg_,
                const float* __restrict__ Vg_, const int* __restrict__ maskg,
                float* __restrict__ Og_)
{
    extern __shared__ float sm[];
    const uint32_t sb = smem_u32(sm);
    uint32_t* KHW = (uint32_t*)(sm + W_KH);
    uint32_t* KLW = (uint32_t*)(sm + W_KL);

    const int tid  = threadIdx.x;
    const int wid  = tid >> 5;
    const int lane = tid & 31;
    const int r    = lane >> 2;
    const int c    = lane & 3;

    float* PS = sm + W_PS + wid * (16 * VSTR);

    const int bh = blockIdx.y;
    const int b  = bh >> 3;
    const int q0 = blockIdx.x * BM;

    const float* Qg = Qg_ + ((size_t)bh * SEQ + q0 + wid * 16) * DH;
    const float* Kg = Kg_ + (size_t)bh * SEQ * DH;
    const float* Vg = Vg_ + (size_t)bh * SEQ * DH;
    const int*   mg = maskg + (size_t)b * SEQ;
    float* Og = Og_ + ((size_t)bh * SEQ + q0 + wid * 16) * DH;

    const int pkey = tid >> 4;          // prefetch: key row this thread covers
    const int pj   = tid & 15;          // d-group (4 floats)

    // ---- prologue: issue tile-0 loads ----
    float4 kpre[8];
    {
        #pragma unroll
        for (int i = 0; i < 8; i++)
            cpa16(sb + (W_VS0 + (pkey + i * 8) * VSTR + 4 * pj) * 4,
                  Vg + (size_t)(pkey + i * 8) * DH + 4 * pj);
        if (tid < BN) cpa4(sb + (W_MSK + tid) * 4, mg + tid);
        CP_COMMIT();
        #pragma unroll
        for (int i = 0; i < 8; i++)
            kpre[i] = *(const float4*)(Kg + (size_t)(pkey + i * 8) * DH + 4 * pj);
    }

    // ---- Q fragments, packed bf16 hi/lo: frag j = rowHalf + 2*colHalf ----
    uint32_t qh[4][4], ql[4][4];
    #pragma unroll
    for (int kt = 0; kt < 4; kt++) {
        #pragma unroll
        for (int rh = 0; rh < 2; rh++) {
            #pragma unroll
            for (int ch = 0; ch < 2; ch++) {
                int row = r + rh * 8;
                int col = kt * 16 + 2 * c + ch * 8;
                float2 v = *(const float2*)(Qg + row * DH + col);
                uint32_t h = bfpk(v.y, v.x);
                qh[kt][rh + 2 * ch] = h;
                ql[kt][rh + 2 * ch] = bfpk(v.y - bfhi_f(h), v.x - bflo_f(h));
            }
        }
    }

    float o[8][4];
    #pragma unroll
    for (int nt = 0; nt < 8; nt++)
        #pragma unroll
        for (int j = 0; j < 4; j++) o[nt][j] = 0.f;
    float lsum0 = 0.f, lsum1 = 0.f;

    #pragma unroll 1
    for (int t = 0; t < NTILES; t++) {
        const int buf = t & 1;
        float* VS = sm + (buf ? W_VS1 : W_VS0);
        const int* MSK = (const int*)(sm + W_MSK + buf * 64);

        CP_WAIT0();
        __syncthreads();

        // ---- convert K regs -> bf16 hi/lo smem ----
        #pragma unroll
        for (int i = 0; i < 8; i++) {
            float4 k4 = kpre[i];
            int key = pkey + i * 8;
            uint32_t h01 = bfpk(k4.y, k4.x);
            uint32_t h23 = bfpk(k4.w, k4.z);
            uint32_t l01 = bfpk(k4.y - bfhi_f(h01), k4.x - bflo_f(h01));
            uint32_t l23 = bfpk(k4.w - bfhi_f(h23), k4.z - bflo_f(h23));
            *(uint2*)(KHW + key * KSTRW + 2 * pj) = make_uint2(h01, h23);
            *(uint2*)(KLW + key * KSTRW + 2 * pj) = make_uint2(l01, l23);
        }
        // ---- round V in place to tf32 (rna) ----
        #pragma unroll
        for (int i = 0; i < 8; i++) {
            float* vp = VS + (pkey + i * 8) * VSTR + 4 * pj;
            float4 v = *(float4*)vp;
            *(uint4*)vp = make_uint4(f2tf(v.x), f2tf(v.y), f2tf(v.z), f2tf(v.w));
        }
        __syncthreads();

        // ---- issue next tile's loads (overlap with compute below) ----
        if (t + 1 < NTILES) {
            const int k1 = (t + 1) * BN;
            const uint32_t vb = (t + 1) & 1;
            #pragma unroll
            for (int i = 0; i < 8; i++)
                cpa16(sb + ((vb ? W_VS1 : W_VS0) + (pkey + i * 8) * VSTR + 4 * pj) * 4,
                      Vg + (size_t)(k1 + pkey + i * 8) * DH + 4 * pj);
            if (tid < BN) cpa4(sb + (W_MSK + vb * 64 + tid) * 4, mg + k1 + tid);
            CP_COMMIT();
            #pragma unroll
            for (int i = 0; i < 8; i++)
                kpre[i] = *(const float4*)(Kg + (size_t)(k1 + pkey + i * 8) * DH + 4 * pj);
        }

        // ---- S = Qh*Kh + Ql*Kh + Qh*Kl (bf16 m16n8k16) ----
        float s[8][4];
        #pragma unroll
        for (int nt = 0; nt < 8; nt++)
            #pragma unroll
            for (int j = 0; j < 4; j++) s[nt][j] = 0.f;

        #pragma unroll
        for (int kt = 0; kt < 4; kt++) {
            #pragma unroll
            for (int nt = 0; nt < 8; nt++) {
                const uint32_t* kh = KHW + (nt * 8 + r) * KSTRW + kt * 8 + c;
                const uint32_t* kl = KLW + (nt * 8 + r) * KSTRW + kt * 8 + c;
                uint32_t bh0 = kh[0], bh1 = kh[4];
                uint32_t bl0 = kl[0], bl1 = kl[4];
                mma_bf16(s[nt], qh[kt], bh0, bh1);
                mma_bf16(s[nt], ql[kt], bh0, bh1);
                mma_bf16(s[nt], qh[kt], bl0, bl1);
            }
        }

        // ---- softmax: p = exp2(14.4269504*(tanh(s/8)-1)), masked -> 0 ----
        #pragma unroll
        for (int nt = 0; nt < 8; nt++) {
            int m0 = MSK[nt * 8 + 2 * c];
            int m1 = MSK[nt * 8 + 2 * c + 1];
            float p[4];
            #pragma unroll
            for (int j = 0; j < 4; j++) {
                float sv = s[nt][j];
                float ax = fabsf(sv) * 0.125f;
                float e2 = ex2f(ax * -2.8853900817779268f);
                float tt = 1.f - 2.f * e2 * rcpf(1.f + e2);
                float ts = copysignf(tt, sv);
                float pv = ex2f(14.4269504088896f * (ts - 1.f));
                pv = ((j & 1) ? m1 : m0) ? 0.f : pv;
                p[j] = __uint_as_float(f2tf(pv));
            }
            lsum0 += p[0] + p[1];
            lsum1 += p[2] + p[3];
            *(float2*)(PS + r * VSTR + nt * 8 + 2 * c)       = make_float2(p[0], p[1]);
            *(float2*)(PS + (r + 8) * VSTR + nt * 8 + 2 * c) = make_float2(p[2], p[3]);
        }
        __syncwarp();

        // ---- O += P * V (tf32 m16n8k8) ----
        #pragma unroll
        for (int kt = 0; kt < 8; kt++) {
            uint32_t a[4];
            a[0] = __float_as_uint(PS[r * VSTR + kt * 8 + c]);
            a[1] = __float_as_uint(PS[(r + 8) * VSTR + kt * 8 + c]);
            a[2] = __float_as_uint(PS[r * VSTR + kt * 8 + c + 4]);
            a[3] = __float_as_uint(PS[(r + 8) * VSTR + kt * 8 + c + 4]);
            #pragma unroll
            for (int nt = 0; nt < 8; nt++) {
                uint32_t b0 = __float_as_uint(VS[(kt * 8 + c) * VSTR + nt * 8 + r]);
                uint32_t b1 = __float_as_uint(VS[(kt * 8 + c + 4) * VSTR + nt * 8 + r]);
                mma_tf32(o[nt], a, b0, b1);
            }
        }
    }

    // ---- row sums across quad, normalize, store ----
    lsum0 += __shfl_xor_sync(0xffffffffu, lsum0, 1);
    lsum0 += __shfl_xor_sync(0xffffffffu, lsum0, 2);
    lsum1 += __shfl_xor_sync(0xffffffffu, lsum1, 1);
    lsum1 += __shfl_xor_sync(0xffffffffu, lsum1, 2);
    float inv0 = rcpf(lsum0);
    float inv1 = rcpf(lsum1);
    #pragma unroll
    for (int nt = 0; nt < 8; nt++) {
        int col = nt * 8 + 2 * c;
        *(float2*)(Og + r * DH + col)       = make_float2(o[nt][0] * inv0, o[nt][1] * inv0);
        *(float2*)(Og + (r + 8) * DH + col) = make_float2(o[nt][2] * inv1, o[nt][3] * inv1);
    }
}

extern "C" void kernel_launch(void* const* d_in, const int* in_sizes, int n_in,
                              void* d_out, int out_size)
{
    const float* Q = (const float*)d_in[0];
    const float* K = (const float*)d_in[1];
    const float* V = (const float*)d_in[2];
    const int* mask = (const int*)d_in[3];
    float* out = (float*)d_out;

    cudaFuncSetAttribute(attn_mma_kernel,
                         cudaFuncAttributeMaxDynamicSharedMemorySize, SMEM_BYTES);

    dim3 grid(SEQ / BM, BATCH * HEADS);
    attn_mma_kernel<<<grid, 128, SMEM_BYTES>>>(Q, K, V, mask, out);
}

// round 7
// speedup vs baseline: 2.6870x; 1.0042x over previous
#include <cuda_runtime.h>
#include <cstdint>
#include <math.h>

#define BATCH 8
#define HEADS 8
#define SEQ   2048
#define DH    64
#define BM    64
#define BN    64
#define NTILES (SEQ / BN)

#define VSTR  68     // f32 V staging stride (words)
#define KSTRW 36     // bf16 tile row stride (words; 72 bf16, pad 8)

#define W_VSTG 0                       // 64*68 = 4352 words
#define W_KH   4352                    // 64*36 = 2304 words each
#define W_KL   (W_KH + 2304)
#define W_VH   (W_KL + 2304)
#define W_VL   (W_VH + 2304)
#define W_MSK  (W_VL + 2304)           // 2*64 ints (double buffered)
#define SMEM_WORDS (W_MSK + 128)
#define SMEM_BYTES (SMEM_WORDS * 4)

__device__ __forceinline__ uint32_t smem_u32(const void* p) {
    uint32_t a;
    asm("{ .reg .u64 t; cvta.to.shared.u64 t, %1; cvt.u32.u64 %0, t; }" : "=r"(a) : "l"(p));
    return a;
}
__device__ __forceinline__ float ex2f(float x) {
    float r; asm("ex2.approx.f32 %0, %1;" : "=f"(r) : "f"(x)); return r;
}
__device__ __forceinline__ float rcpf(float x) {
    float r; asm("rcp.approx.f32 %0, %1;" : "=f"(r) : "f"(x)); return r;
}
// pack two f32 -> bf16x2 (first operand -> HIGH half)
__device__ __forceinline__ uint32_t bfpk(float hi, float lo) {
    uint32_t r; asm("cvt.rn.bf16x2.f32 %0, %1, %2;" : "=r"(r) : "f"(hi), "f"(lo)); return r;
}
__device__ __forceinline__ float bflo_f(uint32_t p) { return __uint_as_float(p << 16); }
__device__ __forceinline__ float bfhi_f(uint32_t p) { return __uint_as_float(p & 0xFFFF0000u); }

__device__ __forceinline__ void mma_bf16(float* d, const uint32_t* a, uint32_t b0, uint32_t b1) {
    asm volatile(
        "mma.sync.aligned.m16n8k16.row.col.f32.bf16.bf16.f32 "
        "{%0,%1,%2,%3}, {%4,%5,%6,%7}, {%8,%9}, {%0,%1,%2,%3};"
        : "+f"(d[0]), "+f"(d[1]), "+f"(d[2]), "+f"(d[3])
        : "r"(a[0]), "r"(a[1]), "r"(a[2]), "r"(a[3]), "r"(b0), "r"(b1));
}
__device__ __forceinline__ void cpa16(uint32_t dst, const void* src) {
    asm volatile("cp.async.cg.shared.global [%0], [%1], 16;" :: "r"(dst), "l"(src));
}
__device__ __forceinline__ void cpa4(uint32_t dst, const void* src) {
    asm volatile("cp.async.ca.shared.global [%0], [%1], 4;" :: "r"(dst), "l"(src));
}
#define CP_COMMIT() asm volatile("cp.async.commit_group;" ::: "memory")
#define CP_WAIT0()  asm volatile("cp.async.wait_group 0;" ::: "memory")

#define LDSM_X4(r0, r1, r2, r3, adr) \
    asm volatile("ldmatrix.sync.aligned.m8n8.x4.shared.b16 {%0,%1,%2,%3}, [%4];" \
        : "=r"(r0), "=r"(r1), "=r"(r2), "=r"(r3) : "r"(adr))
#define LDSM_X4_T(r0, r1, r2, r3, adr) \
    asm volatile("ldmatrix.sync.aligned.m8n8.x4.trans.shared.b16 {%0,%1,%2,%3}, [%4];" \
        : "=r"(r0), "=r"(r1), "=r"(r2), "=r"(r3) : "r"(adr))

__global__ void __launch_bounds__(128, 3)
attn_mma_kernel(const float* __restrict__ Qg_, const float* __restrict__ Kg_,
                const float* __restrict__ Vg_, const int* __restrict__ maskg,
                float* __restrict__ Og_)
{
    extern __shared__ float sm[];
    const uint32_t sb = smem_u32(sm);
    uint32_t* KHW = (uint32_t*)(sm + W_KH);
    uint32_t* KLW = (uint32_t*)(sm + W_KL);
    uint32_t* VHW = (uint32_t*)(sm + W_VH);
    uint32_t* VLW = (uint32_t*)(sm + W_VL);

    const int tid  = threadIdx.x;
    const int wid  = tid >> 5;
    const int lane = tid & 31;
    const int r    = lane >> 2;
    const int c    = lane & 3;

    const int bh = blockIdx.y;
    const int b  = bh >> 3;
    const int q0 = blockIdx.x * BM;

    const float* Qg = Qg_ + ((size_t)bh * SEQ + q0 + wid * 16) * DH;
    const float* Kg = Kg_ + (size_t)bh * SEQ * DH;
    const float* Vg = Vg_ + (size_t)bh * SEQ * DH;
    const int*   mg = maskg + (size_t)b * SEQ;
    float* Og = Og_ + ((size_t)bh * SEQ + q0 + wid * 16) * DH;

    const int pkey = tid >> 4;
    const int pj   = tid & 15;

    // per-lane ldmatrix base offsets (bytes from region start)
    // S-phase (non-trans): lanes 0-7:m0=(nt,b0) 8-15:m1=(nt,b1) 16-23:m2=(nt+1,b0) 24-31:m3
    const uint32_t lkS = (uint32_t)(((lane >> 4) << 3) + (lane & 7));     // key row within pair
    const uint32_t lwS = (uint32_t)(((lane >> 3) & 1) * 4);               // b0/b1 word sel
    const uint32_t offS = (lkS * KSTRW + lwS) * 4;
    // PV (.trans): m0=(nt,b0 keys0-7) m1=(nt,b1 keys8-15) m2=(nt+1,b0) m3=(nt+1,b1)
    const uint32_t keylP = (uint32_t)((((lane >> 3) & 1) << 3) + (lane & 7));
    const uint32_t dwlP  = (uint32_t)(((lane >> 4) & 1) * 4);
    const uint32_t offP = (keylP * KSTRW + dwlP) * 4;

    // ---- prologue: tile-0 V+mask via cp.async, K via LDG ----
    float4 kpre[8];
    {
        #pragma unroll
        for (int i = 0; i < 8; i++)
            cpa16(sb + (W_VSTG + (pkey + i * 8) * VSTR + 4 * pj) * 4,
                  Vg + (size_t)(pkey + i * 8) * DH + 4 * pj);
        if (tid < BN) cpa4(sb + (W_MSK + tid) * 4, mg + tid);
        CP_COMMIT();
        #pragma unroll
        for (int i = 0; i < 8; i++)
            kpre[i] = *(const float4*)(Kg + (size_t)(pkey + i * 8) * DH + 4 * pj);
    }

    // ---- Q fragments, packed bf16 hi/lo ----
    uint32_t qh[4][4], ql[4][4];
    #pragma unroll
    for (int kt = 0; kt < 4; kt++) {
        #pragma unroll
        for (int rh = 0; rh < 2; rh++) {
            #pragma unroll
            for (int ch = 0; ch < 2; ch++) {
                int row = r + rh * 8;
                int col = kt * 16 + 2 * c + ch * 8;
                float2 v = *(const float2*)(Qg + row * DH + col);
                uint32_t h = bfpk(v.y, v.x);
                qh[kt][rh + 2 * ch] = h;
                ql[kt][rh + 2 * ch] = bfpk(v.y - bfhi_f(h), v.x - bflo_f(h));
            }
        }
    }

    float o[8][4];
    #pragma unroll
    for (int nt = 0; nt < 8; nt++)
        #pragma unroll
        for (int j = 0; j < 4; j++) o[nt][j] = 0.f;
    float lsum0 = 0.f, lsum1 = 0.f;

    #pragma unroll 1
    for (int t = 0; t < NTILES; t++) {
        const int buf = t & 1;
        const int* MSK = (const int*)(sm + W_MSK + buf * 64);

        CP_WAIT0();
        __syncthreads();

        // ---- K regs -> bf16 hi/lo smem ----
        #pragma unroll
        for (int i = 0; i < 8; i++) {
            float4 k4 = kpre[i];
            int key = pkey + i * 8;
            uint32_t h01 = bfpk(k4.y, k4.x);
            uint32_t h23 = bfpk(k4.w, k4.z);
            *(uint2*)(KHW + key * KSTRW + 2 * pj) = make_uint2(h01, h23);
            *(uint2*)(KLW + key * KSTRW + 2 * pj) = make_uint2(
                bfpk(k4.y - bfhi_f(h01), k4.x - bflo_f(h01)),
                bfpk(k4.w - bfhi_f(h23), k4.z - bflo_f(h23)));
        }
        // ---- V staging -> bf16 hi/lo smem ----
        #pragma unroll
        for (int i = 0; i < 8; i++) {
            int key = pkey + i * 8;
            float4 v = *(float4*)(sm + W_VSTG + key * VSTR + 4 * pj);
            uint32_t h01 = bfpk(v.y, v.x);
            uint32_t h23 = bfpk(v.w, v.z);
            *(uint2*)(VHW + key * KSTRW + 2 * pj) = make_uint2(h01, h23);
            *(uint2*)(VLW + key * KSTRW + 2 * pj) = make_uint2(
                bfpk(v.y - bfhi_f(h01), v.x - bflo_f(h01)),
                bfpk(v.w - bfhi_f(h23), v.z - bflo_f(h23)));
        }
        __syncthreads();

        // ---- issue next tile's loads ----
        if (t + 1 < NTILES) {
            const int k1 = (t + 1) * BN;
            const int nb = (t + 1) & 1;
            #pragma unroll
            for (int i = 0; i < 8; i++)
                cpa16(sb + (W_VSTG + (pkey + i * 8) * VSTR + 4 * pj) * 4,
                      Vg + (size_t)(k1 + pkey + i * 8) * DH + 4 * pj);
            if (tid < BN) cpa4(sb + (W_MSK + nb * 64 + tid) * 4, mg + k1 + tid);
            CP_COMMIT();
            #pragma unroll
            for (int i = 0; i < 8; i++)
                kpre[i] = *(const float4*)(Kg + (size_t)(k1 + pkey + i * 8) * DH + 4 * pj);
        }

        // ---- S = Qh*Kh + Ql*Kh + Qh*Kl via ldmatrix ----
        float s[8][4];
        #pragma unroll
        for (int nt = 0; nt < 8; nt++)
            #pragma unroll
            for (int j = 0; j < 4; j++) s[nt][j] = 0.f;

        #pragma unroll
        for (int kt = 0; kt < 4; kt++) {
            #pragma unroll
            for (int np = 0; np < 4; np++) {
                uint32_t adrH = sb + W_KH * 4 + offS + (uint32_t)(np * 2304 + kt * 32);
                uint32_t adrL = sb + W_KL * 4 + offS + (uint32_t)(np * 2304 + kt * 32);
                uint32_t bh0, bh1, bh2, bh3, bl0, bl1, bl2, bl3;
                LDSM_X4(bh0, bh1, bh2, bh3, adrH);
                LDSM_X4(bl0, bl1, bl2, bl3, adrL);
                mma_bf16(s[2*np],   qh[kt], bh0, bh1);
                mma_bf16(s[2*np],   ql[kt], bh0, bh1);
                mma_bf16(s[2*np],   qh[kt], bl0, bl1);
                mma_bf16(s[2*np+1], qh[kt], bh2, bh3);
                mma_bf16(s[2*np+1], ql[kt], bh2, bh3);
                mma_bf16(s[2*np+1], qh[kt], bl2, bl3);
            }
        }

        // ---- softmax -> P hi/lo packed in registers (A-operand layout) ----
        uint32_t pAh[8][2], pAl[8][2];
        #pragma unroll
        for (int nt = 0; nt < 8; nt++) {
            int2 m01 = *(const int2*)(MSK + nt * 8 + 2 * c);
            float ph[4], pl[4];
            #pragma unroll
            for (int j = 0; j < 4; j++) {
                float sv = s[nt][j];
                float ax = fabsf(sv) * 0.125f;
                float e2 = ex2f(ax * -2.8853900817779268f);
                float tt = 1.f - 2.f * e2 * rcpf(1.f + e2);
                float ts = copysignf(tt, sv);
                float pv = ex2f(14.4269504088896f * (ts - 1.f));
                pv = ((j & 1) ? m01.y : m01.x) ? 0.f : pv;
                uint32_t u = bfpk(pv, pv);
                ph[j] = bfhi_f(u);
                float res = pv - ph[j];
                uint32_t ul = bfpk(res, res);
                pl[j] = bfhi_f(ul);
            }
            lsum0 += (ph[0] + pl[0]) + (ph[1] + pl[1]);
            lsum1 += (ph[2] + pl[2]) + (ph[3] + pl[3]);
            pAh[nt][0] = bfpk(ph[1], ph[0]);
            pAh[nt][1] = bfpk(ph[3], ph[2]);
            pAl[nt][0] = bfpk(pl[1], pl[0]);
            pAl[nt][1] = bfpk(pl[3], pl[2]);
        }

        // ---- O += P*V : Ph*Vh + Pl*Vh + Ph*Vl via ldmatrix.trans ----
        #pragma unroll
        for (int kt = 0; kt < 4; kt++) {
            uint32_t ah[4] = { pAh[2*kt][0], pAh[2*kt][1], pAh[2*kt+1][0], pAh[2*kt+1][1] };
            uint32_t al[4] = { pAl[2*kt][0], pAl[2*kt][1], pAl[2*kt+1][0], pAl[2*kt+1][1] };
            #pragma unroll
            for (int np = 0; np < 4; np++) {
                uint32_t adrH = sb + W_VH * 4 + offP + (uint32_t)(kt * 2304 + np * 32);
                uint32_t adrL = sb + W_VL * 4 + offP + (uint32_t)(kt * 2304 + np * 32);
                uint32_t vh0, vh1, vh2, vh3, vl0, vl1, vl2, vl3;
                LDSM_X4_T(vh0, vh1, vh2, vh3, adrH);
                LDSM_X4_T(vl0, vl1, vl2, vl3, adrL);
                mma_bf16(o[2*np],   ah, vh0, vh1);
                mma_bf16(o[2*np],   al, vh0, vh1);
                mma_bf16(o[2*np],   ah, vl0, vl1);
                mma_bf16(o[2*np+1], ah, vh2, vh3);
                mma_bf16(o[2*np+1], al, vh2, vh3);
                mma_bf16(o[2*np+1], ah, vl2, vl3);
            }
        }
    }

    // ---- row sums across quad, normalize, store ----
    lsum0 += __shfl_xor_sync(0xffffffffu, lsum0, 1);
    lsum0 += __shfl_xor_sync(0xffffffffu, lsum0, 2);
    lsum1 += __shfl_xor_sync(0xffffffffu, lsum1, 1);
    lsum1 += __shfl_xor_sync(0xffffffffu, lsum1, 2);
    float inv0 = rcpf(lsum0);
    float inv1 = rcpf(lsum1);
    #pragma unroll
    for (int nt = 0; nt < 8; nt++) {
        int col = nt * 8 + 2 * c;
        *(float2*)(Og + r * DH + col)       = make_float2(o[nt][0] * inv0, o[nt][1] * inv0);
        *(float2*)(Og + (r + 8) * DH + col) = make_float2(o[nt][2] * inv1, o[nt][3] * inv1);
    }
}

extern "C" void kernel_launch(void* const* d_in, const int* in_sizes, int n_in,
                              void* d_out, int out_size)
{
    const float* Q = (const float*)d_in[0];
    const float* K = (const float*)d_in[1];
    const float* V = (const float*)d_in[2];
    const int* mask = (const int*)d_in[3];
    float* out = (float*)d_out;

    cudaFuncSetAttribute(attn_mma_kernel,
                         cudaFuncAttributeMaxDynamicSharedMemorySize, SMEM_BYTES);

    dim3 grid(SEQ / BM, BATCH * HEADS);
    attn_mma_kernel<<<grid, 128, SMEM_BYTES>>>(Q, K, V, mask, out);
}

// round 8
// speedup vs baseline: 3.9481x; 1.4693x over previous
#include <cuda_runtime.h>
#include <cstdint>
#include <math.h>

#define BATCH 8
#define HEADS 8
#define SEQ   2048
#define DH    64
#define BM    64
#define BN    64
#define NTILES (SEQ / BN)

#define KSTRW 36                 // bf16 tile row stride in words (72 bf16, pad 8)
#define TILE_WORDS 2304          // 64 rows * 36 words
#define BLK_WORDS  (4 * TILE_WORDS)   // KH,KL,VH,VL per tile = 9216 words

// smem: double-buffered tile block + double-buffered mask
#define W_MSK  (2 * BLK_WORDS)
#define SMEM_WORDS (W_MSK + 128)
#define SMEM_BYTES (SMEM_WORDS * 4)

// precomputed bf16 hi/lo K/V tiles: [bh][tile][4*2304 words]
__device__ __align__(16) uint32_t g_kv[BATCH * HEADS][NTILES][BLK_WORDS];

__device__ __forceinline__ uint32_t smem_u32(const void* p) {
    uint32_t a;
    asm("{ .reg .u64 t; cvta.to.shared.u64 t, %1; cvt.u32.u64 %0, t; }" : "=r"(a) : "l"(p));
    return a;
}
__device__ __forceinline__ float ex2f(float x) {
    float r; asm("ex2.approx.f32 %0, %1;" : "=f"(r) : "f"(x)); return r;
}
__device__ __forceinline__ float rcpf(float x) {
    float r; asm("rcp.approx.f32 %0, %1;" : "=f"(r) : "f"(x)); return r;
}
__device__ __forceinline__ uint32_t bfpk(float hi, float lo) {   // hi -> upper half
    uint32_t r; asm("cvt.rn.bf16x2.f32 %0, %1, %2;" : "=r"(r) : "f"(hi), "f"(lo)); return r;
}
__device__ __forceinline__ float bflo_f(uint32_t p) { return __uint_as_float(p << 16); }
__device__ __forceinline__ float bfhi_f(uint32_t p) { return __uint_as_float(p & 0xFFFF0000u); }
// pack hi16(b):hi16(a) -> {b.hi, a.hi}  (a in low half)
__device__ __forceinline__ uint32_t prmt7632(uint32_t a, uint32_t b) {
    uint32_t d; asm("prmt.b32 %0, %1, %2, 0x7632;" : "=r"(d) : "r"(a), "r"(b)); return d;
}
__device__ __forceinline__ void mma_bf16(float* d, const uint32_t* a, uint32_t b0, uint32_t b1) {
    asm volatile(
        "mma.sync.aligned.m16n8k16.row.col.f32.bf16.bf16.f32 "
        "{%0,%1,%2,%3}, {%4,%5,%6,%7}, {%8,%9}, {%0,%1,%2,%3};"
        : "+f"(d[0]), "+f"(d[1]), "+f"(d[2]), "+f"(d[3])
        : "r"(a[0]), "r"(a[1]), "r"(a[2]), "r"(a[3]), "r"(b0), "r"(b1));
}
__device__ __forceinline__ void cpa16(uint32_t dst, const void* src) {
    asm volatile("cp.async.cg.shared.global [%0], [%1], 16;" :: "r"(dst), "l"(src));
}
__device__ __forceinline__ void cpa4(uint32_t dst, const void* src) {
    asm volatile("cp.async.ca.shared.global [%0], [%1], 4;" :: "r"(dst), "l"(src));
}
#define CP_COMMIT() asm volatile("cp.async.commit_group;" ::: "memory")
#define CP_WAIT0()  asm volatile("cp.async.wait_group 0;" ::: "memory")

#define LDSM_X4(r0, r1, r2, r3, adr) \
    asm volatile("ldmatrix.sync.aligned.m8n8.x4.shared.b16 {%0,%1,%2,%3}, [%4];" \
        : "=r"(r0), "=r"(r1), "=r"(r2), "=r"(r3) : "r"(adr))
#define LDSM_X4_T(r0, r1, r2, r3, adr) \
    asm volatile("ldmatrix.sync.aligned.m8n8.x4.trans.shared.b16 {%0,%1,%2,%3}, [%4];" \
        : "=r"(r0), "=r"(r1), "=r"(r2), "=r"(r3) : "r"(adr))

// ---------------- pre-pass: K,V f32 -> bf16 hi/lo tiles in gmem scratch ----------------
__global__ void __launch_bounds__(128)
prep_kernel(const float* __restrict__ Kg_, const float* __restrict__ Vg_)
{
    const int tile = blockIdx.x;
    const int bh   = blockIdx.y;
    const int tid  = threadIdx.x;
    const int pkey = tid >> 4;
    const int pj   = tid & 15;

    const float* Kg = Kg_ + ((size_t)bh * SEQ + tile * BN) * DH;
    const float* Vg = Vg_ + ((size_t)bh * SEQ + tile * BN) * DH;
    uint32_t* dst = g_kv[bh][tile];

    #pragma unroll
    for (int i = 0; i < 8; i++) {
        int key = pkey + i * 8;
        float4 k4 = *(const float4*)(Kg + (size_t)key * DH + 4 * pj);
        uint32_t h01 = bfpk(k4.y, k4.x);
        uint32_t h23 = bfpk(k4.w, k4.z);
        *(uint2*)(dst + key * KSTRW + 2 * pj) = make_uint2(h01, h23);
        *(uint2*)(dst + TILE_WORDS + key * KSTRW + 2 * pj) = make_uint2(
            bfpk(k4.y - bfhi_f(h01), k4.x - bflo_f(h01)),
            bfpk(k4.w - bfhi_f(h23), k4.z - bflo_f(h23)));
        float4 v4 = *(const float4*)(Vg + (size_t)key * DH + 4 * pj);
        uint32_t g01 = bfpk(v4.y, v4.x);
        uint32_t g23 = bfpk(v4.w, v4.z);
        *(uint2*)(dst + 2 * TILE_WORDS + key * KSTRW + 2 * pj) = make_uint2(g01, g23);
        *(uint2*)(dst + 3 * TILE_WORDS + key * KSTRW + 2 * pj) = make_uint2(
            bfpk(v4.y - bfhi_f(g01), v4.x - bflo_f(g01)),
            bfpk(v4.w - bfhi_f(g23), v4.z - bflo_f(g23)));
    }
}

// ---------------- main attention kernel ----------------
__global__ void __launch_bounds__(128, 3)
attn_mma_kernel(const float* __restrict__ Qg_, const int* __restrict__ maskg,
                float* __restrict__ Og_)
{
    extern __shared__ float sm[];
    const uint32_t sb = smem_u32(sm);

    const int tid  = threadIdx.x;
    const int wid  = tid >> 5;
    const int lane = tid & 31;
    const int r    = lane >> 2;
    const int c    = lane & 3;

    const int bh = blockIdx.y;
    const int b  = bh >> 3;
    const int q0 = blockIdx.x * BM;

    const float* Qg = Qg_ + ((size_t)bh * SEQ + q0 + wid * 16) * DH;
    const int*   mg = maskg + (size_t)b * SEQ;
    float* Og = Og_ + ((size_t)bh * SEQ + q0 + wid * 16) * DH;
    const uint32_t* kv = &g_kv[bh][0][0];

    // per-lane ldmatrix byte offsets (within a region)
    const uint32_t lkS = (uint32_t)(((lane >> 4) << 3) + (lane & 7));
    const uint32_t lwS = (uint32_t)(((lane >> 3) & 1) * 4);
    const uint32_t offS = (lkS * KSTRW + lwS) * 4;
    const uint32_t keylP = (uint32_t)((((lane >> 3) & 1) << 3) + (lane & 7));
    const uint32_t dwlP  = (uint32_t)(((lane >> 4) & 1) * 4);
    const uint32_t offP = (keylP * KSTRW + dwlP) * 4;

    // ---- prologue: stage tile 0 ----
    {
        const uint32_t* src = kv;           // tile 0
        #pragma unroll
        for (int i = 0; i < 18; i++) {
            int idx = tid + i * 128;
            cpa16(sb + (uint32_t)idx * 16u, src + idx * 4);
        }
        if (tid < BN) cpa4(sb + (W_MSK + tid) * 4, mg + tid);
        CP_COMMIT();
    }

    // ---- Q fragments, packed bf16 hi/lo ----
    uint32_t qh[4][4], ql[4][4];
    #pragma unroll
    for (int kt = 0; kt < 4; kt++) {
        #pragma unroll
        for (int rh = 0; rh < 2; rh++) {
            #pragma unroll
            for (int ch = 0; ch < 2; ch++) {
                int row = r + rh * 8;
                int col = kt * 16 + 2 * c + ch * 8;
                float2 v = *(const float2*)(Qg + row * DH + col);
                uint32_t h = bfpk(v.y, v.x);
                qh[kt][rh + 2 * ch] = h;
                ql[kt][rh + 2 * ch] = bfpk(v.y - bfhi_f(h), v.x - bflo_f(h));
            }
        }
    }

    float o[8][4];
    #pragma unroll
    for (int nt = 0; nt < 8; nt++)
        #pragma unroll
        for (int j = 0; j < 4; j++) o[nt][j] = 0.f;
    float lsum0 = 0.f, lsum1 = 0.f;

    #pragma unroll 1
    for (int t = 0; t < NTILES; t++) {
        const int buf = t & 1;
        const uint32_t bufb = sb + (buf ? (uint32_t)(BLK_WORDS * 4) : 0u);
        const int* MSK = (const int*)(sm + W_MSK + buf * 64);

        CP_WAIT0();
        __syncthreads();

        // ---- stage tile t+1 into the other buffer ----
        if (t + 1 < NTILES) {
            const uint32_t* src = kv + (size_t)(t + 1) * BLK_WORDS;
            const uint32_t dstb = sb + (((t + 1) & 1) ? (uint32_t)(BLK_WORDS * 4) : 0u);
            #pragma unroll
            for (int i = 0; i < 18; i++) {
                int idx = tid + i * 128;
                cpa16(dstb + (uint32_t)idx * 16u, src + idx * 4);
            }
            if (tid < BN) cpa4(sb + (W_MSK + ((t + 1) & 1) * 64 + tid) * 4, mg + (t + 1) * BN + tid);
            CP_COMMIT();
        }

        // ---- S = Qh*Kh + Ql*Kh + Qh*Kl ----
        float s[8][4];
        #pragma unroll
        for (int nt = 0; nt < 8; nt++)
            #pragma unroll
            for (int j = 0; j < 4; j++) s[nt][j] = 0.f;

        #pragma unroll
        for (int kt = 0; kt < 4; kt++) {
            #pragma unroll
            for (int np = 0; np < 4; np++) {
                uint32_t adrH = bufb + offS + (uint32_t)(np * 2304 + kt * 32);
                uint32_t adrL = adrH + (uint32_t)(TILE_WORDS * 4);
                uint32_t bh0, bh1, bh2, bh3, bl0, bl1, bl2, bl3;
                LDSM_X4(bh0, bh1, bh2, bh3, adrH);
                LDSM_X4(bl0, bl1, bl2, bl3, adrL);
                mma_bf16(s[2*np],   qh[kt], bh0, bh1);
                mma_bf16(s[2*np],   ql[kt], bh0, bh1);
                mma_bf16(s[2*np],   qh[kt], bl0, bl1);
                mma_bf16(s[2*np+1], qh[kt], bh2, bh3);
                mma_bf16(s[2*np+1], ql[kt], bh2, bh3);
                mma_bf16(s[2*np+1], qh[kt], bl2, bl3);
            }
        }

        // ---- softmax: p = exp2(28.8539*(sigmoid(s/4)-1)); mask -> 0 ----
        uint32_t pAh[8][2], pAl[8][2];
        #pragma unroll
        for (int nt = 0; nt < 8; nt++) {
            int2 m01 = *(const int2*)(MSK + nt * 8 + 2 * c);
            float pv[4];
            #pragma unroll
            for (int j = 0; j < 4; j++) {
                float u  = ex2f(s[nt][j] * -0.36067376022224087f);  // e^{-s/4}
                float sg = rcpf(1.f + u);
                float e  = ex2f(fmaf(sg, 28.853900817779268f, -28.853900817779268f));
                pv[j] = ((j & 1) ? m01.y : m01.x) ? 0.f : e;
            }
            lsum0 += pv[0] + pv[1];
            lsum1 += pv[2] + pv[3];
            uint32_t b0 = __float_as_uint(pv[0]), b1 = __float_as_uint(pv[1]);
            uint32_t b2 = __float_as_uint(pv[2]), b3 = __float_as_uint(pv[3]);
            pAh[nt][0] = prmt7632(b0, b1);
            pAh[nt][1] = prmt7632(b2, b3);
            pAl[nt][0] = bfpk(pv[1] - bfhi_f(b1), pv[0] - bfhi_f(b0));
            pAl[nt][1] = bfpk(pv[3] - bfhi_f(b3), pv[2] - bfhi_f(b2));
        }

        // ---- O += P*V : Ph*Vh + Pl*Vh + Ph*Vl ----
        #pragma unroll
        for (int kt = 0; kt < 4; kt++) {
            uint32_t ah[4] = { pAh[2*kt][0], pAh[2*kt][1], pAh[2*kt+1][0], pAh[2*kt+1][1] };
            uint32_t al[4] = { pAl[2*kt][0], pAl[2*kt][1], pAl[2*kt+1][0], pAl[2*kt+1][1] };
            #pragma unroll
            for (int np = 0; np < 4; np++) {
                uint32_t adrH = bufb + (uint32_t)(2 * TILE_WORDS * 4) + offP +
                                (uint32_t)(kt * 2304 + np * 32);
                uint32_t adrL = adrH + (uint32_t)(TILE_WORDS * 4);
                uint32_t vh0, vh1, vh2, vh3, vl0, vl1, vl2, vl3;
                LDSM_X4_T(vh0, vh1, vh2, vh3, adrH);
                LDSM_X4_T(vl0, vl1, vl2, vl3, adrL);
                mma_bf16(o[2*np],   ah, vh0, vh1);
                mma_bf16(o[2*np],   al, vh0, vh1);
                mma_bf16(o[2*np],   ah, vl0, vl1);
                mma_bf16(o[2*np+1], ah, vh2, vh3);
                mma_bf16(o[2*np+1], al, vh2, vh3);
                mma_bf16(o[2*np+1], ah, vl2, vl3);
            }
        }
    }

    // ---- quad reduce, normalize, store ----
    lsum0 += __shfl_xor_sync(0xffffffffu, lsum0, 1);
    lsum0 += __shfl_xor_sync(0xffffffffu, lsum0, 2);
    lsum1 += __shfl_xor_sync(0xffffffffu, lsum1, 1);
    lsum1 += __shfl_xor_sync(0xffffffffu, lsum1, 2);
    float inv0 = rcpf(lsum0);
    float inv1 = rcpf(lsum1);
    #pragma unroll
    for (int nt = 0; nt < 8; nt++) {
        int col = nt * 8 + 2 * c;
        *(float2*)(Og + r * DH + col)       = make_float2(o[nt][0] * inv0, o[nt][1] * inv0);
        *(float2*)(Og + (r + 8) * DH + col) = make_float2(o[nt][2] * inv1, o[nt][3] * inv1);
    }
}

extern "C" void kernel_launch(void* const* d_in, const int* in_sizes, int n_in,
                              void* d_out, int out_size)
{
    const float* Q = (const float*)d_in[0];
    const float* K = (const float*)d_in[1];
    const float* V = (const float*)d_in[2];
    const int* mask = (const int*)d_in[3];
    float* out = (float*)d_out;

    cudaFuncSetAttribute(attn_mma_kernel,
                         cudaFuncAttributeMaxDynamicSharedMemorySize, SMEM_BYTES);

    dim3 pgrid(NTILES, BATCH * HEADS);
    prep_kernel<<<pgrid, 128>>>(K, V);

    dim3 grid(SEQ / BM, BATCH * HEADS);
    attn_mma_kernel<<<grid, 128, SMEM_BYTES>>>(Q, mask, out);
}

// round 11
// speedup vs baseline: 4.8517x; 1.2289x over previous
#include <cuda_runtime.h>
#include <cstdint>
#include <math.h>

#define BATCH 8
#define HEADS 8
#define SEQ   2048
#define DH    64
#define BM    64
#define BN    64
#define NTILES (SEQ / BN)

#define KSTRW 36                 // tile row stride in words (72 b16 elems, pad 8)
#define TILE_WORDS 2304          // 64 rows * 36 words
#define BLK_WORDS  (3 * TILE_WORDS)   // KH, KL (bf16 hi/lo), V (fp16) = 6912 words

// smem: double-buffered tile block + double-buffered mask
#define W_MSK  (2 * BLK_WORDS)
#define SMEM_WORDS (W_MSK + 128)
#define SMEM_BYTES (SMEM_WORDS * 4)

// precomputed tiles: [bh][tile][KH|KL|VF16]
__device__ __align__(16) uint32_t g_kv[BATCH * HEADS][NTILES][BLK_WORDS];

__device__ __forceinline__ uint32_t smem_u32(const void* p) {
    uint32_t a;
    asm("{ .reg .u64 t; cvta.to.shared.u64 t, %1; cvt.u32.u64 %0, t; }" : "=r"(a) : "l"(p));
    return a;
}
__device__ __forceinline__ float ex2f(float x) {
    float r; asm("ex2.approx.f32 %0, %1;" : "=f"(r) : "f"(x)); return r;
}
__device__ __forceinline__ float rcpf(float x) {
    float r; asm("rcp.approx.f32 %0, %1;" : "=f"(r) : "f"(x)); return r;
}
__device__ __forceinline__ uint32_t bfpk(float hi, float lo) {   // first -> upper half
    uint32_t r; asm("cvt.rn.bf16x2.f32 %0, %1, %2;" : "=r"(r) : "f"(hi), "f"(lo)); return r;
}
__device__ __forceinline__ uint32_t h2pk(float hi, float lo) {   // fp16x2, first -> upper
    uint32_t r; asm("cvt.rn.f16x2.f32 %0, %1, %2;" : "=r"(r) : "f"(hi), "f"(lo)); return r;
}
__device__ __forceinline__ float2 h2unpk(uint32_t p) {
    float lo, hi;
    asm("{ .reg .f16 a, b;\n\t mov.b32 {a, b}, %2;\n\t"
        "cvt.f32.f16 %0, a;\n\t cvt.f32.f16 %1, b; }"
        : "=f"(lo), "=f"(hi) : "r"(p));
    return make_float2(lo, hi);
}
__device__ __forceinline__ float bflo_f(uint32_t p) { return __uint_as_float(p << 16); }
__device__ __forceinline__ float bfhi_f(uint32_t p) { return __uint_as_float(p & 0xFFFF0000u); }

__device__ __forceinline__ void mma_bf16(float* d, const uint32_t* a, uint32_t b0, uint32_t b1) {
    asm volatile(
        "mma.sync.aligned.m16n8k16.row.col.f32.bf16.bf16.f32 "
        "{%0,%1,%2,%3}, {%4,%5,%6,%7}, {%8,%9}, {%0,%1,%2,%3};"
        : "+f"(d[0]), "+f"(d[1]), "+f"(d[2]), "+f"(d[3])
        : "r"(a[0]), "r"(a[1]), "r"(a[2]), "r"(a[3]), "r"(b0), "r"(b1));
}
__device__ __forceinline__ void mma_f16(float* d, const uint32_t* a, uint32_t b0, uint32_t b1) {
    asm volatile(
        "mma.sync.aligned.m16n8k16.row.col.f32.f16.f16.f32 "
        "{%0,%1,%2,%3}, {%4,%5,%6,%7}, {%8,%9}, {%0,%1,%2,%3};"
        : "+f"(d[0]), "+f"(d[1]), "+f"(d[2]), "+f"(d[3])
        : "r"(a[0]), "r"(a[1]), "r"(a[2]), "r"(a[3]), "r"(b0), "r"(b1));
}
__device__ __forceinline__ void cpa16(uint32_t dst, const void* src) {
    asm volatile("cp.async.cg.shared.global [%0], [%1], 16;" :: "r"(dst), "l"(src));
}
__device__ __forceinline__ void cpa4(uint32_t dst, const void* src) {
    asm volatile("cp.async.ca.shared.global [%0], [%1], 4;" :: "r"(dst), "l"(src));
}
#define CP_COMMIT() asm volatile("cp.async.commit_group;" ::: "memory")
#define CP_WAIT0()  asm volatile("cp.async.wait_group 0;" ::: "memory")

#define LDSM_X4(r0, r1, r2, r3, adr) \
    asm volatile("ldmatrix.sync.aligned.m8n8.x4.shared.b16 {%0,%1,%2,%3}, [%4];" \
        : "=r"(r0), "=r"(r1), "=r"(r2), "=r"(r3) : "r"(adr))
#define LDSM_X4_T(r0, r1, r2, r3, adr) \
    asm volatile("ldmatrix.sync.aligned.m8n8.x4.trans.shared.b16 {%0,%1,%2,%3}, [%4];" \
        : "=r"(r0), "=r"(r1), "=r"(r2), "=r"(r3) : "r"(adr))

// ---------------- pre-pass: K -> bf16 hi/lo, V -> fp16 ----------------
__global__ void __launch_bounds__(128)
prep_kernel(const float* __restrict__ Kg_, const float* __restrict__ Vg_)
{
    const int tile = blockIdx.x;
    const int bh   = blockIdx.y;
    const int tid  = threadIdx.x;
    const int pkey = tid >> 4;
    const int pj   = tid & 15;

    const float* Kg = Kg_ + ((size_t)bh * SEQ + tile * BN) * DH;
    const float* Vg = Vg_ + ((size_t)bh * SEQ + tile * BN) * DH;
    uint32_t* dst = g_kv[bh][tile];

    #pragma unroll
    for (int i = 0; i < 8; i++) {
        int key = pkey + i * 8;
        float4 k4 = *(const float4*)(Kg + (size_t)key * DH + 4 * pj);
        uint32_t h01 = bfpk(k4.y, k4.x);
        uint32_t h23 = bfpk(k4.w, k4.z);
        *(uint2*)(dst + key * KSTRW + 2 * pj) = make_uint2(h01, h23);
        *(uint2*)(dst + TILE_WORDS + key * KSTRW + 2 * pj) = make_uint2(
            bfpk(k4.y - bfhi_f(h01), k4.x - bflo_f(h01)),
            bfpk(k4.w - bfhi_f(h23), k4.z - bflo_f(h23)));
        float4 v4 = *(const float4*)(Vg + (size_t)key * DH + 4 * pj);
        *(uint2*)(dst + 2 * TILE_WORDS + key * KSTRW + 2 * pj) =
            make_uint2(h2pk(v4.y, v4.x), h2pk(v4.w, v4.z));
    }
}

// ---------------- main attention kernel ----------------
__global__ void __launch_bounds__(128, 3)
attn_mma_kernel(const float* __restrict__ Qg_, const int* __restrict__ maskg,
                float* __restrict__ Og_)
{
    extern __shared__ float sm[];
    const uint32_t sb = smem_u32(sm);

    const int tid  = threadIdx.x;
    const int wid  = tid >> 5;
    const int lane = tid & 31;
    const int r    = lane >> 2;
    const int c    = lane & 3;

    const int bh = blockIdx.y;
    const int b  = bh >> 3;
    const int q0 = blockIdx.x * BM;

    const float* Qg = Qg_ + ((size_t)bh * SEQ + q0 + wid * 16) * DH;
    const int*   mg = maskg + (size_t)b * SEQ;
    float* Og = Og_ + ((size_t)bh * SEQ + q0 + wid * 16) * DH;
    const uint32_t* kv = &g_kv[bh][0][0];

    // per-lane ldmatrix byte offsets (within a region)
    const uint32_t lkS = (uint32_t)(((lane >> 4) << 3) + (lane & 7));
    const uint32_t lwS = (uint32_t)(((lane >> 3) & 1) * 4);
    const uint32_t offS = (lkS * KSTRW + lwS) * 4;
    const uint32_t keylP = (uint32_t)((((lane >> 3) & 1) << 3) + (lane & 7));
    const uint32_t dwlP  = (uint32_t)(((lane >> 4) & 1) * 4);
    const uint32_t offP = (keylP * KSTRW + dwlP) * 4;

    // ---- prologue: stage tile 0 (6912 words = 1728 16B chunks) ----
    {
        const uint32_t* src = kv;
        #pragma unroll
        for (int i = 0; i < 13; i++) {
            int idx = tid + i * 128;
            cpa16(sb + (uint32_t)idx * 16u, src + idx * 4);
        }
        if (tid < 64) cpa16(sb + (uint32_t)(tid + 1664) * 16u, src + (tid + 1664) * 4);
        if (tid < BN) cpa4(sb + (W_MSK + tid) * 4, mg + tid);
        CP_COMMIT();
    }

    // ---- Q fragments, packed bf16 hi/lo ----
    uint32_t qh[4][4], ql[4][4];
    #pragma unroll
    for (int kt = 0; kt < 4; kt++) {
        #pragma unroll
        for (int rh = 0; rh < 2; rh++) {
            #pragma unroll
            for (int ch = 0; ch < 2; ch++) {
                int row = r + rh * 8;
                int col = kt * 16 + 2 * c + ch * 8;
                float2 v = *(const float2*)(Qg + row * DH + col);
                uint32_t h = bfpk(v.y, v.x);
                qh[kt][rh + 2 * ch] = h;
                ql[kt][rh + 2 * ch] = bfpk(v.y - bfhi_f(h), v.x - bflo_f(h));
            }
        }
    }

    float o[8][4];
    #pragma unroll
    for (int nt = 0; nt < 8; nt++)
        #pragma unroll
        for (int j = 0; j < 4; j++) o[nt][j] = 0.f;
    float lsum0 = 0.f, lsum1 = 0.f;

    #pragma unroll 1
    for (int t = 0; t < NTILES; t++) {
        const int buf = t & 1;
        const uint32_t bufb = sb + (buf ? (uint32_t)(BLK_WORDS * 4) : 0u);
        const int* MSK = (const int*)(sm + W_MSK + buf * 64);

        CP_WAIT0();
        __syncthreads();

        // ---- stage tile t+1 into the other buffer ----
        if (t + 1 < NTILES) {
            const uint32_t* src = kv + (size_t)(t + 1) * BLK_WORDS;
            const uint32_t dstb = sb + (((t + 1) & 1) ? (uint32_t)(BLK_WORDS * 4) : 0u);
            #pragma unroll
            for (int i = 0; i < 13; i++) {
                int idx = tid + i * 128;
                cpa16(dstb + (uint32_t)idx * 16u, src + idx * 4);
            }
            if (tid < 64) cpa16(dstb + (uint32_t)(tid + 1664) * 16u, src + (tid + 1664) * 4);
            if (tid < BN) cpa4(sb + (W_MSK + ((t + 1) & 1) * 64 + tid) * 4, mg + (t + 1) * BN + tid);
            CP_COMMIT();
        }

        // ---- S = Qh*Kh + Ql*Kh + Qh*Kl ----
        float s[8][4];
        #pragma unroll
        for (int nt = 0; nt < 8; nt++)
            #pragma unroll
            for (int j = 0; j < 4; j++) s[nt][j] = 0.f;

        #pragma unroll
        for (int kt = 0; kt < 4; kt++) {
            #pragma unroll
            for (int np = 0; np < 4; np++) {
                uint32_t adrH = bufb + offS + (uint32_t)(np * 2304 + kt * 32);
                uint32_t adrL = adrH + (uint32_t)(TILE_WORDS * 4);
                uint32_t bh0, bh1, bh2, bh3, bl0, bl1, bl2, bl3;
                LDSM_X4(bh0, bh1, bh2, bh3, adrH);
                LDSM_X4(bl0, bl1, bl2, bl3, adrL);
                mma_bf16(s[2*np],   qh[kt], bh0, bh1);
                mma_bf16(s[2*np],   ql[kt], bh0, bh1);
                mma_bf16(s[2*np],   qh[kt], bl0, bl1);
                mma_bf16(s[2*np+1], qh[kt], bh2, bh3);
                mma_bf16(s[2*np+1], ql[kt], bh2, bh3);
                mma_bf16(s[2*np+1], qh[kt], bl2, bl3);
            }
        }

        // ---- softmax: p = exp2(28.8539*(sigmoid(s/4)-1)); mask -> 0; pack fp16 ----
        uint32_t pA[8][2];
        #pragma unroll
        for (int nt = 0; nt < 8; nt++) {
            int2 m01 = *(const int2*)(MSK + nt * 8 + 2 * c);
            float pv[4];
            #pragma unroll
            for (int j = 0; j < 4; j++) {
                float u  = ex2f(s[nt][j] * -0.36067376022224087f);  // e^{-s/4}
                float sg = rcpf(1.f + u);
                float e  = ex2f(fmaf(sg, 28.853900817779268f, -28.853900817779268f));
                pv[j] = ((j & 1) ? m01.y : m01.x) ? 0.f : e;
            }
            uint32_t pk0 = h2pk(pv[1], pv[0]);
            uint32_t pk1 = h2pk(pv[3], pv[2]);
            pA[nt][0] = pk0;
            pA[nt][1] = pk1;
            float2 f0 = h2unpk(pk0);   // lsum from fp16-rounded weights (matches numerator)
            float2 f1 = h2unpk(pk1);
            lsum0 += f0.x + f0.y;
            lsum1 += f1.x + f1.y;
        }

        // ---- O += P*V (single fp16 product) ----
        #pragma unroll
        for (int kt = 0; kt < 4; kt++) {
            uint32_t a[4] = { pA[2*kt][0], pA[2*kt][1], pA[2*kt+1][0], pA[2*kt+1][1] };
            #pragma unroll
            for (int np = 0; np < 4; np++) {
                uint32_t adrV = bufb + (uint32_t)(2 * TILE_WORDS * 4) + offP +
                                (uint32_t)(kt * 2304 + np * 32);
                uint32_t v0, v1, v2, v3;
                LDSM_X4_T(v0, v1, v2, v3, adrV);
                mma_f16(o[2*np],   a, v0, v1);
                mma_f16(o[2*np+1], a, v2, v3);
            }
        }
    }

    // ---- quad reduce, normalize, store ----
    lsum0 += __shfl_xor_sync(0xffffffffu, lsum0, 1);
    lsum0 += __shfl_xor_sync(0xffffffffu, lsum0, 2);
    lsum1 += __shfl_xor_sync(0xffffffffu, lsum1, 1);
    lsum1 += __shfl_xor_sync(0xffffffffu, lsum1, 2);
    float inv0 = rcpf(lsum0);
    float inv1 = rcpf(lsum1);
    #pragma unroll
    for (int nt = 0; nt < 8; nt++) {
        int col = nt * 8 + 2 * c;
        *(float2*)(Og + r * DH + col)       = make_float2(o[nt][0] * inv0, o[nt][1] * inv0);
        *(float2*)(Og + (r + 8) * DH + col) = make_float2(o[nt][2] * inv1, o[nt][3] * inv1);
    }
}

extern "C" void kernel_launch(void* const* d_in, const int* in_sizes, int n_in,
                              void* d_out, int out_size)
{
    const float* Q = (const float*)d_in[0];
    const float* K = (const float*)d_in[1];
    const float* V = (const float*)d_in[2];
    const int* mask = (const int*)d_in[3];
    float* out = (float*)d_out;

    cudaFuncSetAttribute(attn_mma_kernel,
                         cudaFuncAttributeMaxDynamicSharedMemorySize, SMEM_BYTES);

    dim3 pgrid(NTILES, BATCH * HEADS);
    prep_kernel<<<pgrid, 128>>>(K, V);

    dim3 grid(SEQ / BM, BATCH * HEADS);
    attn_mma_kernel<<<grid, 128, SMEM_BYTES>>>(Q, mask, out);
}

// round 13
// speedup vs baseline: 6.2885x; 1.2962x over previous
#include <cuda_runtime.h>
#include <cstdint>
#include <math.h>

#define BATCH 8
#define HEADS 8
#define SEQ   2048
#define DH    64
#define BM    64
#define BN    64
#define NTILES (SEQ / BN)

#define KSTRW 36                 // tile row stride in words (72 b16 elems, pad 8)
#define TILE_WORDS 2304          // 64 rows * 36 words
#define BLK_WORDS  (2 * TILE_WORDS)   // K (fp16), V (fp16) = 4608 words

// smem: double-buffered tile block + double-buffered mask
#define W_MSK  (2 * BLK_WORDS)
#define SMEM_WORDS (W_MSK + 128)
#define SMEM_BYTES (SMEM_WORDS * 4)

// Q pre-scale so that u = 2^s  equals  e^{qk/4}:  log2(e)/4
#define QSCALE 0.36067376022224087f

// precomputed tiles: [bh][tile][K_f16 | V_f16]
__device__ __align__(16) uint32_t g_kv[BATCH * HEADS][NTILES][BLK_WORDS];

__device__ __forceinline__ uint32_t smem_u32(const void* p) {
    uint32_t a;
    asm("{ .reg .u64 t; cvta.to.shared.u64 t, %1; cvt.u32.u64 %0, t; }" : "=r"(a) : "l"(p));
    return a;
}
__device__ __forceinline__ float ex2f(float x) {
    float r; asm("ex2.approx.f32 %0, %1;" : "=f"(r) : "f"(x)); return r;
}
__device__ __forceinline__ float rcpf(float x) {
    float r; asm("rcp.approx.f32 %0, %1;" : "=f"(r) : "f"(x)); return r;
}
__device__ __forceinline__ uint32_t h2pk(float hi, float lo) {   // fp16x2, first -> upper
    uint32_t r; asm("cvt.rn.f16x2.f32 %0, %1, %2;" : "=r"(r) : "f"(hi), "f"(lo)); return r;
}
__device__ __forceinline__ float2 h2unpk(uint32_t p) {
    float lo, hi;
    asm("{ .reg .f16 a, b;\n\t mov.b32 {a, b}, %2;\n\t"
        "cvt.f32.f16 %0, a;\n\t cvt.f32.f16 %1, b; }"
        : "=f"(lo), "=f"(hi) : "r"(p));
    return make_float2(lo, hi);
}

__device__ __forceinline__ void mma_f16(float* d, const uint32_t* a, uint32_t b0, uint32_t b1) {
    asm volatile(
        "mma.sync.aligned.m16n8k16.row.col.f32.f16.f16.f32 "
        "{%0,%1,%2,%3}, {%4,%5,%6,%7}, {%8,%9}, {%0,%1,%2,%3};"
        : "+f"(d[0]), "+f"(d[1]), "+f"(d[2]), "+f"(d[3])
        : "r"(a[0]), "r"(a[1]), "r"(a[2]), "r"(a[3]), "r"(b0), "r"(b1));
}
// init form: d = a*b + 0 (no read of d)
__device__ __forceinline__ void mma_f16_z(float* d, const uint32_t* a, uint32_t b0, uint32_t b1) {
    asm volatile(
        "mma.sync.aligned.m16n8k16.row.col.f32.f16.f16.f32 "
        "{%0,%1,%2,%3}, {%4,%5,%6,%7}, {%8,%9}, {%10,%10,%10,%10};"
        : "=f"(d[0]), "=f"(d[1]), "=f"(d[2]), "=f"(d[3])
        : "r"(a[0]), "r"(a[1]), "r"(a[2]), "r"(a[3]), "r"(b0), "r"(b1), "f"(0.f));
}
__device__ __forceinline__ void cpa16(uint32_t dst, const void* src) {
    asm volatile("cp.async.cg.shared.global [%0], [%1], 16;" :: "r"(dst), "l"(src));
}
__device__ __forceinline__ void cpa4(uint32_t dst, const void* src) {
    asm volatile("cp.async.ca.shared.global [%0], [%1], 4;" :: "r"(dst), "l"(src));
}
#define CP_COMMIT() asm volatile("cp.async.commit_group;" ::: "memory")
#define CP_WAIT0()  asm volatile("cp.async.wait_group 0;" ::: "memory")

#define LDSM_X4(r0, r1, r2, r3, adr) \
    asm volatile("ldmatrix.sync.aligned.m8n8.x4.shared.b16 {%0,%1,%2,%3}, [%4];" \
        : "=r"(r0), "=r"(r1), "=r"(r2), "=r"(r3) : "r"(adr))
#define LDSM_X4_T(r0, r1, r2, r3, adr) \
    asm volatile("ldmatrix.sync.aligned.m8n8.x4.trans.shared.b16 {%0,%1,%2,%3}, [%4];" \
        : "=r"(r0), "=r"(r1), "=r"(r2), "=r"(r3) : "r"(adr))

// ---------------- pre-pass: K,V -> fp16 tiles ----------------
__global__ void __launch_bounds__(128)
prep_kernel(const float* __restrict__ Kg_, const float* __restrict__ Vg_)
{
    const int tile = blockIdx.x;
    const int bh   = blockIdx.y;
    const int tid  = threadIdx.x;
    const int pkey = tid >> 4;
    const int pj   = tid & 15;

    const float* Kg = Kg_ + ((size_t)bh * SEQ + tile * BN) * DH;
    const float* Vg = Vg_ + ((size_t)bh * SEQ + tile * BN) * DH;
    uint32_t* dst = g_kv[bh][tile];

    #pragma unroll
    for (int i = 0; i < 8; i++) {
        int key = pkey + i * 8;
        float4 k4 = *(const float4*)(Kg + (size_t)key * DH + 4 * pj);
        *(uint2*)(dst + key * KSTRW + 2 * pj) =
            make_uint2(h2pk(k4.y, k4.x), h2pk(k4.w, k4.z));
        float4 v4 = *(const float4*)(Vg + (size_t)key * DH + 4 * pj);
        *(uint2*)(dst + TILE_WORDS + key * KSTRW + 2 * pj) =
            make_uint2(h2pk(v4.y, v4.x), h2pk(v4.w, v4.z));
    }
}

// ---------------- main attention kernel ----------------
__global__ void __launch_bounds__(128, 3)
attn_mma_kernel(const float* __restrict__ Qg_, const int* __restrict__ maskg,
                float* __restrict__ Og_)
{
    extern __shared__ float sm[];
    const uint32_t sb = smem_u32(sm);

    const int tid  = threadIdx.x;
    const int wid  = tid >> 5;
    const int lane = tid & 31;
    const int r    = lane >> 2;
    const int c    = lane & 3;

    const int bh = blockIdx.y;
    const int b  = bh >> 3;
    const int q0 = blockIdx.x * BM;

    const float* Qg = Qg_ + ((size_t)bh * SEQ + q0 + wid * 16) * DH;
    const int*   mg = maskg + (size_t)b * SEQ;
    float* Og = Og_ + ((size_t)bh * SEQ + q0 + wid * 16) * DH;
    const uint32_t* kv = &g_kv[bh][0][0];

    // per-lane ldmatrix byte offsets (within a region)
    const uint32_t lkS = (uint32_t)(((lane >> 4) << 3) + (lane & 7));
    const uint32_t lwS = (uint32_t)(((lane >> 3) & 1) * 4);
    const uint32_t offS = (lkS * KSTRW + lwS) * 4;
    const uint32_t keylP = (uint32_t)((((lane >> 3) & 1) << 3) + (lane & 7));
    const uint32_t dwlP  = (uint32_t)(((lane >> 4) & 1) * 4);
    const uint32_t offP = (keylP * KSTRW + dwlP) * 4;

    // ---- prologue: stage tile 0 (4608 words = 1152 16B chunks, 9/thread) ----
    {
        const uint32_t* src = kv;
        #pragma unroll
        for (int i = 0; i < 9; i++) {
            int idx = tid + i * 128;
            cpa16(sb + (uint32_t)idx * 16u, src + idx * 4);
        }
        if (tid < BN) cpa4(sb + (W_MSK + tid) * 4, mg + tid);
        CP_COMMIT();
    }

    // ---- Q fragments: pre-scaled by QSCALE, packed fp16 hi/lo ----
    uint32_t qh[4][4], ql[4][4];
    #pragma unroll
    for (int kt = 0; kt < 4; kt++) {
        #pragma unroll
        for (int rh = 0; rh < 2; rh++) {
            #pragma unroll
            for (int ch = 0; ch < 2; ch++) {
                int row = r + rh * 8;
                int col = kt * 16 + 2 * c + ch * 8;
                float2 v = *(const float2*)(Qg + row * DH + col);
                v.x *= QSCALE; v.y *= QSCALE;
                uint32_t h = h2pk(v.y, v.x);
                qh[kt][rh + 2 * ch] = h;
                float2 hv = h2unpk(h);
                ql[kt][rh + 2 * ch] = h2pk(v.y - hv.y, v.x - hv.x);
            }
        }
    }

    float o[8][4];
    #pragma unroll
    for (int nt = 0; nt < 8; nt++)
        #pragma unroll
        for (int j = 0; j < 4; j++) o[nt][j] = 0.f;
    float lsum0 = 0.f, lsum1 = 0.f;

    #pragma unroll 1
    for (int t = 0; t < NTILES; t++) {
        const int buf = t & 1;
        const uint32_t bufb = sb + (buf ? (uint32_t)(BLK_WORDS * 4) : 0u);
        const int* MSK = (const int*)(sm + W_MSK + buf * 64);

        CP_WAIT0();
        __syncthreads();

        // ---- stage tile t+1 into the other buffer ----
        if (t + 1 < NTILES) {
            const uint32_t* src = kv + (size_t)(t + 1) * BLK_WORDS;
            const uint32_t dstb = sb + (((t + 1) & 1) ? (uint32_t)(BLK_WORDS * 4) : 0u);
            #pragma unroll
            for (int i = 0; i < 9; i++) {
                int idx = tid + i * 128;
                cpa16(dstb + (uint32_t)idx * 16u, src + idx * 4);
            }
            if (tid < BN) cpa4(sb + (W_MSK + ((t + 1) & 1) * 64 + tid) * 4, mg + (t + 1) * BN + tid);
            CP_COMMIT();
        }

        // ---- S = Qh*K + Ql*K  (fp16, K single-rounded) ----
        float s[8][4];
        #pragma unroll
        for (int kt = 0; kt < 4; kt++) {
            #pragma unroll
            for (int np = 0; np < 4; np++) {
                uint32_t adrH = bufb + offS + (uint32_t)(np * 2304 + kt * 32);
                uint32_t bh0, bh1, bh2, bh3;
                LDSM_X4(bh0, bh1, bh2, bh3, adrH);
                if (kt == 0) {
                    mma_f16_z(s[2*np],   qh[0], bh0, bh1);
                    mma_f16_z(s[2*np+1], qh[0], bh2, bh3);
                } else {
                    mma_f16(s[2*np],   qh[kt], bh0, bh1);
                    mma_f16(s[2*np+1], qh[kt], bh2, bh3);
                }
                mma_f16(s[2*np],   ql[kt], bh0, bh1);
                mma_f16(s[2*np+1], ql[kt], bh2, bh3);
            }
        }

        // ---- softmax: p = 2^(-28.8539/(1+2^s)); mask -> 0; pack fp16 ----
        uint32_t pA[8][2];
        #pragma unroll
        for (int nt = 0; nt < 8; nt++) {
            int2 m01 = *(const int2*)(MSK + nt * 8 + 2 * c);
            float pv[4];
            #pragma unroll
            for (int j = 0; j < 4; j++) {
                float u  = ex2f(s[nt][j]);                 // e^{qk/4}
                float rr = rcpf(1.f + u);
                float e  = ex2f(rr * -28.853900817779268f);
                pv[j] = ((j & 1) ? m01.y : m01.x) ? 0.f : e;
            }
            lsum0 += pv[0] + pv[1];
            lsum1 += pv[2] + pv[3];
            pA[nt][0] = h2pk(pv[1], pv[0]);
            pA[nt][1] = h2pk(pv[3], pv[2]);
        }

        // ---- O += P*V (single fp16 product) ----
        #pragma unroll
        for (int kt = 0; kt < 4; kt++) {
            uint32_t a[4] = { pA[2*kt][0], pA[2*kt][1], pA[2*kt+1][0], pA[2*kt+1][1] };
            #pragma unroll
            for (int np = 0; np < 4; np++) {
                uint32_t adrV = bufb + (uint32_t)(TILE_WORDS * 4) + offP +
                                (uint32_t)(kt * 2304 + np * 32);
                uint32_t v0, v1, v2, v3;
                LDSM_X4_T(v0, v1, v2, v3, adrV);
                mma_f16(o[2*np],   a, v0, v1);
                mma_f16(o[2*np+1], a, v2, v3);
            }
        }
    }

    // ---- quad reduce, normalize, store ----
    lsum0 += __shfl_xor_sync(0xffffffffu, lsum0, 1);
    lsum0 += __shfl_xor_sync(0xffffffffu, lsum0, 2);
    lsum1 += __shfl_xor_sync(0xffffffffu, lsum1, 1);
    lsum1 += __shfl_xor_sync(0xffffffffu, lsum1, 2);
    float inv0 = rcpf(lsum0);
    float inv1 = rcpf(lsum1);
    #pragma unroll
    for (int nt = 0; nt < 8; nt++) {
        int col = nt * 8 + 2 * c;
        *(float2*)(Og + r * DH + col)       = make_float2(o[nt][0] * inv0, o[nt][1] * inv0);
        *(float2*)(Og + (r + 8) * DH + col) = make_float2(o[nt][2] * inv1, o[nt][3] * inv1);
    }
}

extern "C" void kernel_launch(void* const* d_in, const int* in_sizes, int n_in,
                              void* d_out, int out_size)
{
    const float* Q = (const float*)d_in[0];
    const float* K = (const float*)d_in[1];
    const float* V = (const float*)d_in[2];
    const int* mask = (const int*)d_in[3];
    float* out = (float*)d_out;

    cudaFuncSetAttribute(attn_mma_kernel,
                         cudaFuncAttributeMaxDynamicSharedMemorySize, SMEM_BYTES);

    dim3 pgrid(NTILES, BATCH * HEADS);
    prep_kernel<<<pgrid, 128>>>(K, V);

    dim3 grid(SEQ / BM, BATCH * HEADS);
    attn_mma_kernel<<<grid, 128, SMEM_BYTES>>>(Q, mask, out);
}

// round 14
// speedup vs baseline: 11.5857x; 1.8424x over previous
#include <cuda_runtime.h>
#include <cstdint>
#include <math.h>

#define BATCH 8
#define HEADS 8
#define SEQ   2048
#define DH    64
#define BM    64
#define BN    64
#define MAXTILES (SEQ / BN)

#define KSTRW 36                 // tile row stride in words (72 b16 elems, pad 8)
#define TILE_WORDS 2304          // 64 rows * 36 words
#define BLK_WORDS  (2 * TILE_WORDS)   // K (fp16), V (fp16) = 4608 words

// smem: double-buffered tile block
#define SMEM_WORDS (2 * BLK_WORDS)
#define SMEM_BYTES (SMEM_WORDS * 4)

// Q pre-scale so that u = 2^s equals e^{qk/4}: log2(e)/4
#define QSCALE 0.36067376022224087f

// compacted K/V tiles: [bh][tile][K_f16 | V_f16]
__device__ __align__(16) uint32_t g_kv[BATCH * HEADS][MAXTILES][BLK_WORDS];
__device__ int g_idx[BATCH][SEQ];   // compacted original key indices
__device__ int g_cnt[BATCH];        // number of unmasked keys

__device__ __forceinline__ uint32_t smem_u32(const void* p) {
    uint32_t a;
    asm("{ .reg .u64 t; cvta.to.shared.u64 t, %1; cvt.u32.u64 %0, t; }" : "=r"(a) : "l"(p));
    return a;
}
__device__ __forceinline__ float ex2f(float x) {
    float r; asm("ex2.approx.f32 %0, %1;" : "=f"(r) : "f"(x)); return r;
}
__device__ __forceinline__ float rcpf(float x) {
    float r; asm("rcp.approx.f32 %0, %1;" : "=f"(r) : "f"(x)); return r;
}
__device__ __forceinline__ uint32_t h2pk(float hi, float lo) {   // fp16x2, first -> upper
    uint32_t r; asm("cvt.rn.f16x2.f32 %0, %1, %2;" : "=r"(r) : "f"(hi), "f"(lo)); return r;
}
__device__ __forceinline__ float2 h2unpk(uint32_t p) {
    float lo, hi;
    asm("{ .reg .f16 a, b;\n\t mov.b32 {a, b}, %2;\n\t"
        "cvt.f32.f16 %0, a;\n\t cvt.f32.f16 %1, b; }"
        : "=f"(lo), "=f"(hi) : "r"(p));
    return make_float2(lo, hi);
}

__device__ __forceinline__ void mma_f16(float* d, const uint32_t* a, uint32_t b0, uint32_t b1) {
    asm volatile(
        "mma.sync.aligned.m16n8k16.row.col.f32.f16.f16.f32 "
        "{%0,%1,%2,%3}, {%4,%5,%6,%7}, {%8,%9}, {%0,%1,%2,%3};"
        : "+f"(d[0]), "+f"(d[1]), "+f"(d[2]), "+f"(d[3])
        : "r"(a[0]), "r"(a[1]), "r"(a[2]), "r"(a[3]), "r"(b0), "r"(b1));
}
__device__ __forceinline__ void mma_f16_z(float* d, const uint32_t* a, uint32_t b0, uint32_t b1) {
    asm volatile(
        "mma.sync.aligned.m16n8k16.row.col.f32.f16.f16.f32 "
        "{%0,%1,%2,%3}, {%4,%5,%6,%7}, {%8,%9}, {%10,%10,%10,%10};"
        : "=f"(d[0]), "=f"(d[1]), "=f"(d[2]), "=f"(d[3])
        : "r"(a[0]), "r"(a[1]), "r"(a[2]), "r"(a[3]), "r"(b0), "r"(b1), "f"(0.f));
}
__device__ __forceinline__ void cpa16(uint32_t dst, const void* src) {
    asm volatile("cp.async.cg.shared.global [%0], [%1], 16;" :: "r"(dst), "l"(src));
}
#define CP_COMMIT() asm volatile("cp.async.commit_group;" ::: "memory")
#define CP_WAIT0()  asm volatile("cp.async.wait_group 0;" ::: "memory")

#define LDSM_X4(r0, r1, r2, r3, adr) \
    asm volatile("ldmatrix.sync.aligned.m8n8.x4.shared.b16 {%0,%1,%2,%3}, [%4];" \
        : "=r"(r0), "=r"(r1), "=r"(r2), "=r"(r3) : "r"(adr))
#define LDSM_X4_T(r0, r1, r2, r3, adr) \
    asm volatile("ldmatrix.sync.aligned.m8n8.x4.trans.shared.b16 {%0,%1,%2,%3}, [%4];" \
        : "=r"(r0), "=r"(r1), "=r"(r2), "=r"(r3) : "r"(adr))

// ---------- pass 1: per-batch warp ballot prefix-scan of unmasked keys ----------
__global__ void __launch_bounds__(32)
compact_kernel(const int* __restrict__ maskg)
{
    const int b = blockIdx.x;
    const int lane = threadIdx.x;
    const int* mg = maskg + (size_t)b * SEQ;
    int cnt = 0;
    for (int i = 0; i < SEQ / 32; i++) {
        int key = i * 32 + lane;
        int um = (mg[key] == 0);
        unsigned bal = __ballot_sync(0xffffffffu, um);
        int pos = cnt + __popc(bal & ((1u << lane) - 1u));
        if (um) g_idx[b][pos] = key;
        cnt += __popc(bal);
    }
    if (lane == 0) g_cnt[b] = cnt;
}

// ---------- pass 2: gather compacted K,V rows -> fp16 tiles ----------
__global__ void __launch_bounds__(128)
gather_kernel(const float* __restrict__ Kg_, const float* __restrict__ Vg_)
{
    const int tile = blockIdx.x;
    const int bh   = blockIdx.y;
    const int b    = bh >> 3;
    const int tid  = threadIdx.x;
    const int pkey = tid >> 4;
    const int pj   = tid & 15;

    const int cnt = g_cnt[b];
    if (tile * BN >= cnt) return;

    const float* Kg = Kg_ + (size_t)bh * SEQ * DH;
    const float* Vg = Vg_ + (size_t)bh * SEQ * DH;
    uint32_t* dst = g_kv[bh][tile];

    #pragma unroll
    for (int i = 0; i < 8; i++) {
        int slot = tile * BN + pkey + i * 8;
        int key  = pkey + i * 8;
        if (slot < cnt) {
            int src = g_idx[b][slot];
            float4 k4 = *(const float4*)(Kg + (size_t)src * DH + 4 * pj);
            *(uint2*)(dst + key * KSTRW + 2 * pj) =
                make_uint2(h2pk(k4.y, k4.x), h2pk(k4.w, k4.z));
            float4 v4 = *(const float4*)(Vg + (size_t)src * DH + 4 * pj);
            *(uint2*)(dst + TILE_WORDS + key * KSTRW + 2 * pj) =
                make_uint2(h2pk(v4.y, v4.x), h2pk(v4.w, v4.z));
        } else {
            *(uint2*)(dst + key * KSTRW + 2 * pj) = make_uint2(0u, 0u);
            *(uint2*)(dst + TILE_WORDS + key * KSTRW + 2 * pj) = make_uint2(0u, 0u);
        }
    }
}

// ---------------- main attention kernel ----------------
__global__ void __launch_bounds__(128, 3)
attn_mma_kernel(const float* __restrict__ Qg_, float* __restrict__ Og_)
{
    extern __shared__ float sm[];
    const uint32_t sb = smem_u32(sm);

    const int tid  = threadIdx.x;
    const int wid  = tid >> 5;
    const int lane = tid & 31;
    const int r    = lane >> 2;
    const int c    = lane & 3;

    const int bh = blockIdx.y;
    const int b  = bh >> 3;
    const int q0 = blockIdx.x * BM;

    const float* Qg = Qg_ + ((size_t)bh * SEQ + q0 + wid * 16) * DH;
    float* Og = Og_ + ((size_t)bh * SEQ + q0 + wid * 16) * DH;
    const uint32_t* kv = &g_kv[bh][0][0];

    const int cnt   = g_cnt[b];
    const int ntile = (cnt + BN - 1) >> 6;

    // per-lane ldmatrix byte offsets (within a region)
    const uint32_t lkS = (uint32_t)(((lane >> 4) << 3) + (lane & 7));
    const uint32_t lwS = (uint32_t)(((lane >> 3) & 1) * 4);
    const uint32_t offS = (lkS * KSTRW + lwS) * 4;
    const uint32_t keylP = (uint32_t)((((lane >> 3) & 1) << 3) + (lane & 7));
    const uint32_t dwlP  = (uint32_t)(((lane >> 4) & 1) * 4);
    const uint32_t offP = (keylP * KSTRW + dwlP) * 4;

    // ---- prologue: stage tile 0 ----
    {
        const uint32_t* src = kv;
        #pragma unroll
        for (int i = 0; i < 9; i++) {
            int idx = tid + i * 128;
            cpa16(sb + (uint32_t)idx * 16u, src + idx * 4);
        }
        CP_COMMIT();
    }

    // ---- Q fragments: pre-scaled, packed fp16 hi/lo ----
    uint32_t qh[4][4], ql[4][4];
    #pragma unroll
    for (int kt = 0; kt < 4; kt++) {
        #pragma unroll
        for (int rh = 0; rh < 2; rh++) {
            #pragma unroll
            for (int ch = 0; ch < 2; ch++) {
                int row = r + rh * 8;
                int col = kt * 16 + 2 * c + ch * 8;
                float2 v = *(const float2*)(Qg + row * DH + col);
                v.x *= QSCALE; v.y *= QSCALE;
                uint32_t h = h2pk(v.y, v.x);
                qh[kt][rh + 2 * ch] = h;
                float2 hv = h2unpk(h);
                ql[kt][rh + 2 * ch] = h2pk(v.y - hv.y, v.x - hv.x);
            }
        }
    }

    float o[8][4];
    #pragma unroll
    for (int nt = 0; nt < 8; nt++)
        #pragma unroll
        for (int j = 0; j < 4; j++) o[nt][j] = 0.f;
    float lsum0 = 0.f, lsum1 = 0.f;

    #pragma unroll 1
    for (int t = 0; t < ntile; t++) {
        const int buf = t & 1;
        const uint32_t bufb = sb + (buf ? (uint32_t)(BLK_WORDS * 4) : 0u);

        CP_WAIT0();
        __syncthreads();

        // ---- stage tile t+1 ----
        if (t + 1 < ntile) {
            const uint32_t* src = kv + (size_t)(t + 1) * BLK_WORDS;
            const uint32_t dstb = sb + (((t + 1) & 1) ? (uint32_t)(BLK_WORDS * 4) : 0u);
            #pragma unroll
            for (int i = 0; i < 9; i++) {
                int idx = tid + i * 128;
                cpa16(dstb + (uint32_t)idx * 16u, src + idx * 4);
            }
            CP_COMMIT();
        }

        // ---- S = Qh*K + Ql*K ----
        float s[8][4];
        #pragma unroll
        for (int kt = 0; kt < 4; kt++) {
            #pragma unroll
            for (int np = 0; np < 4; np++) {
                uint32_t adrH = bufb + offS + (uint32_t)(np * 2304 + kt * 32);
                uint32_t bh0, bh1, bh2, bh3;
                LDSM_X4(bh0, bh1, bh2, bh3, adrH);
                if (kt == 0) {
                    mma_f16_z(s[2*np],   qh[0], bh0, bh1);
                    mma_f16_z(s[2*np+1], qh[0], bh2, bh3);
                } else {
                    mma_f16(s[2*np],   qh[kt], bh0, bh1);
                    mma_f16(s[2*np+1], qh[kt], bh2, bh3);
                }
                mma_f16(s[2*np],   ql[kt], bh0, bh1);
                mma_f16(s[2*np+1], ql[kt], bh2, bh3);
            }
        }

        // ---- softmax: p = 2^(-28.8539/(1+2^s)); pad slots -> 0 ----
        const int base = t * BN + 2 * c;
        uint32_t pA[8][2];
        #pragma unroll
        for (int nt = 0; nt < 8; nt++) {
            int c0 = base + nt * 8;
            float pv[4];
            #pragma unroll
            for (int j = 0; j < 4; j++) {
                float u  = ex2f(s[nt][j]);
                float rr = rcpf(1.f + u);
                float e  = ex2f(rr * -28.853900817779268f);
                pv[j] = (c0 + (j & 1) < cnt) ? e : 0.f;
            }
            lsum0 += pv[0] + pv[1];
            lsum1 += pv[2] + pv[3];
            pA[nt][0] = h2pk(pv[1], pv[0]);
            pA[nt][1] = h2pk(pv[3], pv[2]);
        }

        // ---- O += P*V ----
        #pragma unroll
        for (int kt = 0; kt < 4; kt++) {
            uint32_t a[4] = { pA[2*kt][0], pA[2*kt][1], pA[2*kt+1][0], pA[2*kt+1][1] };
            #pragma unroll
            for (int np = 0; np < 4; np++) {
                uint32_t adrV = bufb + (uint32_t)(TILE_WORDS * 4) + offP +
                                (uint32_t)(kt * 2304 + np * 32);
                uint32_t v0, v1, v2, v3;
                LDSM_X4_T(v0, v1, v2, v3, adrV);
                mma_f16(o[2*np],   a, v0, v1);
                mma_f16(o[2*np+1], a, v2, v3);
            }
        }
    }

    // ---- quad reduce, normalize, store ----
    lsum0 += __shfl_xor_sync(0xffffffffu, lsum0, 1);
    lsum0 += __shfl_xor_sync(0xffffffffu, lsum0, 2);
    lsum1 += __shfl_xor_sync(0xffffffffu, lsum1, 1);
    lsum1 += __shfl_xor_sync(0xffffffffu, lsum1, 2);
    float inv0 = rcpf(lsum0);
    float inv1 = rcpf(lsum1);
    #pragma unroll
    for (int nt = 0; nt < 8; nt++) {
        int col = nt * 8 + 2 * c;
        *(float2*)(Og + r * DH + col)       = make_float2(o[nt][0] * inv0, o[nt][1] * inv0);
        *(float2*)(Og + (r + 8) * DH + col) = make_float2(o[nt][2] * inv1, o[nt][3] * inv1);
    }
}

extern "C" void kernel_launch(void* const* d_in, const int* in_sizes, int n_in,
                              void* d_out, int out_size)
{
    const float* Q = (const float*)d_in[0];
    const float* K = (const float*)d_in[1];
    const float* V = (const float*)d_in[2];
    const int* mask = (const int*)d_in[3];
    float* out = (float*)d_out;

    cudaFuncSetAttribute(attn_mma_kernel,
                         cudaFuncAttributeMaxDynamicSharedMemorySize, SMEM_BYTES);

    compact_kernel<<<BATCH, 32>>>(mask);

    dim3 ggrid(MAXTILES, BATCH * HEADS);
    gather_kernel<<<ggrid, 128>>>(K, V);

    dim3 grid(SEQ / BM, BATCH * HEADS);
    attn_mma_kernel<<<grid, 128, SMEM_BYTES>>>(Q, out);
}

// round 15
// speedup vs baseline: 13.9100x; 1.2006x over previous
#include <cuda_runtime.h>
#include <cstdint>
#include <math.h>

#define BATCH 8
#define HEADS 8
#define SEQ   2048
#define DH    64
#define BM    64
#define BN    64
#define MAXTILES (SEQ / BN)

#define KSTRW 36                 // tile row stride in words (72 b16 elems, pad 8)
#define TILE_WORDS 2304          // 64 rows * 36 words
#define BLK_WORDS  (2 * TILE_WORDS)   // K (fp16), V (fp16) = 4608 words

#define SMEM_WORDS (2 * BLK_WORDS)
#define SMEM_BYTES (SMEM_WORDS * 4)

// Q pre-scale so that u = 2^s equals e^{qk/4}: log2(e)/4
#define QSCALE 0.36067376022224087f

__device__ __align__(16) uint32_t g_kv[BATCH * HEADS][MAXTILES][BLK_WORDS];
__device__ int g_idx[BATCH][SEQ];
__device__ int g_cnt[BATCH];

__device__ __forceinline__ uint32_t smem_u32(const void* p) {
    uint32_t a;
    asm("{ .reg .u64 t; cvta.to.shared.u64 t, %1; cvt.u32.u64 %0, t; }" : "=r"(a) : "l"(p));
    return a;
}
__device__ __forceinline__ float ex2f(float x) {
    float r; asm("ex2.approx.f32 %0, %1;" : "=f"(r) : "f"(x)); return r;
}
__device__ __forceinline__ float rcpf(float x) {
    float r; asm("rcp.approx.f32 %0, %1;" : "=f"(r) : "f"(x)); return r;
}
__device__ __forceinline__ uint32_t h2pk(float hi, float lo) {   // fp16x2, first -> upper
    uint32_t r; asm("cvt.rn.f16x2.f32 %0, %1, %2;" : "=r"(r) : "f"(hi), "f"(lo)); return r;
}

__device__ __forceinline__ void mma_f16(float* d, const uint32_t* a, uint32_t b0, uint32_t b1) {
    asm volatile(
        "mma.sync.aligned.m16n8k16.row.col.f32.f16.f16.f32 "
        "{%0,%1,%2,%3}, {%4,%5,%6,%7}, {%8,%9}, {%0,%1,%2,%3};"
        : "+f"(d[0]), "+f"(d[1]), "+f"(d[2]), "+f"(d[3])
        : "r"(a[0]), "r"(a[1]), "r"(a[2]), "r"(a[3]), "r"(b0), "r"(b1));
}
__device__ __forceinline__ void mma_f16_z(float* d, const uint32_t* a, uint32_t b0, uint32_t b1) {
    asm volatile(
        "mma.sync.aligned.m16n8k16.row.col.f32.f16.f16.f32 "
        "{%0,%1,%2,%3}, {%4,%5,%6,%7}, {%8,%9}, {%10,%10,%10,%10};"
        : "=f"(d[0]), "=f"(d[1]), "=f"(d[2]), "=f"(d[3])
        : "r"(a[0]), "r"(a[1]), "r"(a[2]), "r"(a[3]), "r"(b0), "r"(b1), "f"(0.f));
}
__device__ __forceinline__ void cpa16(uint32_t dst, const void* src) {
    asm volatile("cp.async.cg.shared.global [%0], [%1], 16;" :: "r"(dst), "l"(src));
}
#define CP_COMMIT() asm volatile("cp.async.commit_group;" ::: "memory")
#define CP_WAIT0()  asm volatile("cp.async.wait_group 0;" ::: "memory")

#define LDSM_X4(r0, r1, r2, r3, adr) \
    asm volatile("ldmatrix.sync.aligned.m8n8.x4.shared.b16 {%0,%1,%2,%3}, [%4];" \
        : "=r"(r0), "=r"(r1), "=r"(r2), "=r"(r3) : "r"(adr))
#define LDSM_X4_T(r0, r1, r2, r3, adr) \
    asm volatile("ldmatrix.sync.aligned.m8n8.x4.trans.shared.b16 {%0,%1,%2,%3}, [%4];" \
        : "=r"(r0), "=r"(r1), "=r"(r2), "=r"(r3) : "r"(adr))

// ---------- pass 1: per-batch 256-thread block scan of unmasked keys ----------
__global__ void __launch_bounds__(256)
compact_kernel(const int* __restrict__ maskg)
{
    __shared__ int wsum[8];
    __shared__ int wpre[8];
    __shared__ int running;
    const int b   = blockIdx.x;
    const int tid = threadIdx.x;
    const int w   = tid >> 5;
    const int lane = tid & 31;
    const int* mg = maskg + (size_t)b * SEQ;

    if (tid == 0) running = 0;
    __syncthreads();

    for (int ch = 0; ch < SEQ / 256; ch++) {
        int key = ch * 256 + tid;
        int um = (mg[key] == 0);
        unsigned bal = __ballot_sync(0xffffffffu, um);
        if (lane == 0) wsum[w] = __popc(bal);
        __syncthreads();
        if (tid == 0) {
            int acc = running;
            #pragma unroll
            for (int i = 0; i < 8; i++) { wpre[i] = acc; acc += wsum[i]; }
            running = acc;
        }
        __syncthreads();
        int pos = wpre[w] + __popc(bal & ((1u << lane) - 1u));
        if (um) g_idx[b][pos] = key;
        __syncthreads();
    }
    if (tid == 0) g_cnt[b] = running;
}

// ---------- pass 2: gather compacted K,V rows -> fp16 tiles ----------
__global__ void __launch_bounds__(128)
gather_kernel(const float* __restrict__ Kg_, const float* __restrict__ Vg_)
{
    const int tile = blockIdx.x;
    const int bh   = blockIdx.y;
    const int b    = bh >> 3;
    const int tid  = threadIdx.x;
    const int pkey = tid >> 4;
    const int pj   = tid & 15;

    const int cnt = g_cnt[b];
    if (tile * BN >= cnt) return;

    const float* Kg = Kg_ + (size_t)bh * SEQ * DH;
    const float* Vg = Vg_ + (size_t)bh * SEQ * DH;
    uint32_t* dst = g_kv[bh][tile];

    #pragma unroll
    for (int i = 0; i < 8; i++) {
        int slot = tile * BN + pkey + i * 8;
        int key  = pkey + i * 8;
        if (slot < cnt) {
            int src = g_idx[b][slot];
            float4 k4 = *(const float4*)(Kg + (size_t)src * DH + 4 * pj);
            *(uint2*)(dst + key * KSTRW + 2 * pj) =
                make_uint2(h2pk(k4.y, k4.x), h2pk(k4.w, k4.z));
            float4 v4 = *(const float4*)(Vg + (size_t)src * DH + 4 * pj);
            *(uint2*)(dst + TILE_WORDS + key * KSTRW + 2 * pj) =
                make_uint2(h2pk(v4.y, v4.x), h2pk(v4.w, v4.z));
        } else {
            *(uint2*)(dst + key * KSTRW + 2 * pj) = make_uint2(0u, 0u);
            *(uint2*)(dst + TILE_WORDS + key * KSTRW + 2 * pj) = make_uint2(0u, 0u);
        }
    }
}

// ---------------- main attention kernel ----------------
__global__ void __launch_bounds__(128, 3)
attn_mma_kernel(const float* __restrict__ Qg_, float* __restrict__ Og_)
{
    extern __shared__ float sm[];
    const uint32_t sb = smem_u32(sm);

    const int tid  = threadIdx.x;
    const int wid  = tid >> 5;
    const int lane = tid & 31;
    const int r    = lane >> 2;
    const int c    = lane & 3;

    const int bh = blockIdx.y;
    const int b  = bh >> 3;
    const int q0 = blockIdx.x * BM;

    const float* Qg = Qg_ + ((size_t)bh * SEQ + q0 + wid * 16) * DH;
    float* Og = Og_ + ((size_t)bh * SEQ + q0 + wid * 16) * DH;
    const uint32_t* kv = &g_kv[bh][0][0];

    const int cnt   = g_cnt[b];
    const int ntile = (cnt + BN - 1) >> 6;

    const uint32_t lkS = (uint32_t)(((lane >> 4) << 3) + (lane & 7));
    const uint32_t lwS = (uint32_t)(((lane >> 3) & 1) * 4);
    const uint32_t offS = (lkS * KSTRW + lwS) * 4;
    const uint32_t keylP = (uint32_t)((((lane >> 3) & 1) << 3) + (lane & 7));
    const uint32_t dwlP  = (uint32_t)(((lane >> 4) & 1) * 4);
    const uint32_t offP = (keylP * KSTRW + dwlP) * 4;

    // ---- prologue: stage tile 0 ----
    {
        const uint32_t* src = kv;
        #pragma unroll
        for (int i = 0; i < 9; i++) {
            int idx = tid + i * 128;
            cpa16(sb + (uint32_t)idx * 16u, src + idx * 4);
        }
        CP_COMMIT();
    }

    // ---- Q fragments: pre-scaled, single fp16 ----
    uint32_t qh[4][4];
    #pragma unroll
    for (int kt = 0; kt < 4; kt++) {
        #pragma unroll
        for (int rh = 0; rh < 2; rh++) {
            #pragma unroll
            for (int ch = 0; ch < 2; ch++) {
                int row = r + rh * 8;
                int col = kt * 16 + 2 * c + ch * 8;
                float2 v = *(const float2*)(Qg + row * DH + col);
                qh[kt][rh + 2 * ch] = h2pk(v.y * QSCALE, v.x * QSCALE);
            }
        }
    }

    float o[8][4];
    #pragma unroll
    for (int nt = 0; nt < 8; nt++)
        #pragma unroll
        for (int j = 0; j < 4; j++) o[nt][j] = 0.f;
    float lsum0 = 0.f, lsum1 = 0.f;

    #pragma unroll 1
    for (int t = 0; t < ntile; t++) {
        const int buf = t & 1;
        const uint32_t bufb = sb + (buf ? (uint32_t)(BLK_WORDS * 4) : 0u);

        CP_WAIT0();
        __syncthreads();

        // ---- stage tile t+1 ----
        if (t + 1 < ntile) {
            const uint32_t* src = kv + (size_t)(t + 1) * BLK_WORDS;
            const uint32_t dstb = sb + (((t + 1) & 1) ? (uint32_t)(BLK_WORDS * 4) : 0u);
            #pragma unroll
            for (int i = 0; i < 9; i++) {
                int idx = tid + i * 128;
                cpa16(dstb + (uint32_t)idx * 16u, src + idx * 4);
            }
            CP_COMMIT();
        }

        // ---- S = Q*K (single fp16 product) ----
        float s[8][4];
        #pragma unroll
        for (int kt = 0; kt < 4; kt++) {
            #pragma unroll
            for (int np = 0; np < 4; np++) {
                uint32_t adrH = bufb + offS + (uint32_t)(np * 2304 + kt * 32);
                uint32_t bh0, bh1, bh2, bh3;
                LDSM_X4(bh0, bh1, bh2, bh3, adrH);
                if (kt == 0) {
                    mma_f16_z(s[2*np],   qh[0], bh0, bh1);
                    mma_f16_z(s[2*np+1], qh[0], bh2, bh3);
                } else {
                    mma_f16(s[2*np],   qh[kt], bh0, bh1);
                    mma_f16(s[2*np+1], qh[kt], bh2, bh3);
                }
            }
        }

        // ---- softmax: p = 2^(-28.8539/(1+2^s)); pads only in last tile ----
        const bool lastt = (t == ntile - 1);
        const int base = t * BN + 2 * c;
        uint32_t pA[8][2];
        #pragma unroll
        for (int nt = 0; nt < 8; nt++) {
            float pv[4];
            #pragma unroll
            for (int j = 0; j < 4; j++) {
                float u  = ex2f(s[nt][j]);
                float rr = rcpf(1.f + u);
                pv[j] = ex2f(rr * -28.853900817779268f);
            }
            if (lastt) {
                int c0 = base + nt * 8;
                #pragma unroll
                for (int j = 0; j < 4; j++)
                    if (c0 + (j & 1) >= cnt) pv[j] = 0.f;
            }
            lsum0 += pv[0] + pv[1];
            lsum1 += pv[2] + pv[3];
            pA[nt][0] = h2pk(pv[1], pv[0]);
            pA[nt][1] = h2pk(pv[3], pv[2]);
        }

        // ---- O += P*V ----
        #pragma unroll
        for (int kt = 0; kt < 4; kt++) {
            uint32_t a[4] = { pA[2*kt][0], pA[2*kt][1], pA[2*kt+1][0], pA[2*kt+1][1] };
            #pragma unroll
            for (int np = 0; np < 4; np++) {
                uint32_t adrV = bufb + (uint32_t)(TILE_WORDS * 4) + offP +
                                (uint32_t)(kt * 2304 + np * 32);
                uint32_t v0, v1, v2, v3;
                LDSM_X4_T(v0, v1, v2, v3, adrV);
                mma_f16(o[2*np],   a, v0, v1);
                mma_f16(o[2*np+1], a, v2, v3);
            }
        }
    }

    // ---- quad reduce, normalize, store ----
    lsum0 += __shfl_xor_sync(0xffffffffu, lsum0, 1);
    lsum0 += __shfl_xor_sync(0xffffffffu, lsum0, 2);
    lsum1 += __shfl_xor_sync(0xffffffffu, lsum1, 1);
    lsum1 += __shfl_xor_sync(0xffffffffu, lsum1, 2);
    float inv0 = rcpf(lsum0);
    float inv1 = rcpf(lsum1);
    #pragma unroll
    for (int nt = 0; nt < 8; nt++) {
        int col = nt * 8 + 2 * c;
        *(float2*)(Og + r * DH + col)       = make_float2(o[nt][0] * inv0, o[nt][1] * inv0);
        *(float2*)(Og + (r + 8) * DH + col) = make_float2(o[nt][2] * inv1, o[nt][3] * inv1);
    }
}

extern "C" void kernel_launch(void* const* d_in, const int* in_sizes, int n_in,
                              void* d_out, int out_size)
{
    const float* Q = (const float*)d_in[0];
    const float* K = (const float*)d_in[1];
    const float* V = (const float*)d_in[2];
    const int* mask = (const int*)d_in[3];
    float* out = (float*)d_out;

    cudaFuncSetAttribute(attn_mma_kernel,
                         cudaFuncAttributeMaxDynamicSharedMemorySize, SMEM_BYTES);

    compact_kernel<<<BATCH, 256>>>(mask);

    dim3 ggrid(MAXTILES, BATCH * HEADS);
    gather_kernel<<<ggrid, 128>>>(K, V);

    dim3 grid(SEQ / BM, BATCH * HEADS);
    attn_mma_kernel<<<grid, 128, SMEM_BYTES>>>(Q, out);
}

// round 16
// speedup vs baseline: 14.3050x; 1.0284x over previous
#include <cuda_runtime.h>
#include <cstdint>
#include <math.h>

#define BATCH 8
#define HEADS 8
#define SEQ   2048
#define DH    64
#define BM    64
#define BN    64
#define MAXTILES (SEQ / BN)

#define KSTRW 36                 // tile row stride in words (72 b16 elems, pad 8)
#define TILE_WORDS 2304          // 64 rows * 36 words
#define BLK_WORDS  (2 * TILE_WORDS)   // K (fp16), V (fp16) = 4608 words

#define SMEM_WORDS (2 * BLK_WORDS)
#define SMEM_BYTES (SMEM_WORDS * 4)

// Q pre-scale so that u = 2^s equals e^{qk/4}: log2(e)/4
#define QSCALE 0.36067376022224087f

__device__ __align__(16) uint32_t g_kv[BATCH * HEADS][MAXTILES][BLK_WORDS];
__device__ int g_idx[BATCH][SEQ];
__device__ int g_cnt[BATCH];

__device__ __forceinline__ uint32_t smem_u32(const void* p) {
    uint32_t a;
    asm("{ .reg .u64 t; cvta.to.shared.u64 t, %1; cvt.u32.u64 %0, t; }" : "=r"(a) : "l"(p));
    return a;
}
__device__ __forceinline__ float ex2f(float x) {
    float r; asm("ex2.approx.f32 %0, %1;" : "=f"(r) : "f"(x)); return r;
}
__device__ __forceinline__ float rcpf(float x) {
    float r; asm("rcp.approx.f32 %0, %1;" : "=f"(r) : "f"(x)); return r;
}
__device__ __forceinline__ uint32_t h2pk(float hi, float lo) {   // fp16x2, first -> upper
    uint32_t r; asm("cvt.rn.f16x2.f32 %0, %1, %2;" : "=r"(r) : "f"(hi), "f"(lo)); return r;
}

__device__ __forceinline__ void mma_f16(float* d, const uint32_t* a, uint32_t b0, uint32_t b1) {
    asm volatile(
        "mma.sync.aligned.m16n8k16.row.col.f32.f16.f16.f32 "
        "{%0,%1,%2,%3}, {%4,%5,%6,%7}, {%8,%9}, {%0,%1,%2,%3};"
        : "+f"(d[0]), "+f"(d[1]), "+f"(d[2]), "+f"(d[3])
        : "r"(a[0]), "r"(a[1]), "r"(a[2]), "r"(a[3]), "r"(b0), "r"(b1));
}
__device__ __forceinline__ void mma_f16_z(float* d, const uint32_t* a, uint32_t b0, uint32_t b1) {
    asm volatile(
        "mma.sync.aligned.m16n8k16.row.col.f32.f16.f16.f32 "
        "{%0,%1,%2,%3}, {%4,%5,%6,%7}, {%8,%9}, {%10,%10,%10,%10};"
        : "=f"(d[0]), "=f"(d[1]), "=f"(d[2]), "=f"(d[3])
        : "r"(a[0]), "r"(a[1]), "r"(a[2]), "r"(a[3]), "r"(b0), "r"(b1), "f"(0.f));
}
__device__ __forceinline__ void cpa16(uint32_t dst, const void* src) {
    asm volatile("cp.async.cg.shared.global [%0], [%1], 16;" :: "r"(dst), "l"(src));
}
#define CP_COMMIT() asm volatile("cp.async.commit_group;" ::: "memory")
#define CP_WAIT0()  asm volatile("cp.async.wait_group 0;" ::: "memory")

#define LDSM_X4(r0, r1, r2, r3, adr) \
    asm volatile("ldmatrix.sync.aligned.m8n8.x4.shared.b16 {%0,%1,%2,%3}, [%4];" \
        : "=r"(r0), "=r"(r1), "=r"(r2), "=r"(r3) : "r"(adr))
#define LDSM_X4_T(r0, r1, r2, r3, adr) \
    asm volatile("ldmatrix.sync.aligned.m8n8.x4.trans.shared.b16 {%0,%1,%2,%3}, [%4];" \
        : "=r"(r0), "=r"(r1), "=r"(r2), "=r"(r3) : "r"(adr))

// ---------- pass 1: per-batch 1024-thread block scan of unmasked keys ----------
__global__ void __launch_bounds__(1024)
compact_kernel(const int* __restrict__ maskg)
{
    __shared__ int wsum[32];
    __shared__ int wpre[32];
    __shared__ int running;
    const int b    = blockIdx.x;
    const int tid  = threadIdx.x;
    const int w    = tid >> 5;
    const int lane = tid & 31;
    const int* mg = maskg + (size_t)b * SEQ;

    if (tid == 0) running = 0;
    __syncthreads();

    #pragma unroll
    for (int ch = 0; ch < SEQ / 1024; ch++) {
        int key = ch * 1024 + tid;
        int um = (mg[key] == 0);
        unsigned bal = __ballot_sync(0xffffffffu, um);
        if (lane == 0) wsum[w] = __popc(bal);
        __syncthreads();
        if (tid == 0) {
            int acc = running;
            #pragma unroll
            for (int i = 0; i < 32; i++) { wpre[i] = acc; acc += wsum[i]; }
            running = acc;
        }
        __syncthreads();
        int pos = wpre[w] + __popc(bal & ((1u << lane) - 1u));
        if (um) g_idx[b][pos] = key;
        __syncthreads();
    }
    if (tid == 0) g_cnt[b] = running;
}

// ---------- pass 2: gather compacted K,V rows -> fp16 tiles (256 thr) ----------
__global__ void __launch_bounds__(256)
gather_kernel(const float* __restrict__ Kg_, const float* __restrict__ Vg_)
{
    const int tile = blockIdx.x;
    const int bh   = blockIdx.y;
    const int b    = bh >> 3;
    const int tid  = threadIdx.x;

    const int cnt = g_cnt[b];
    if (tile * BN >= cnt) return;

    const float* Kg = Kg_ + (size_t)bh * SEQ * DH;
    const float* Vg = Vg_ + (size_t)bh * SEQ * DH;
    uint32_t* dst = g_kv[bh][tile];

    #pragma unroll
    for (int i = 0; i < 4; i++) {
        int idx = tid + i * 256;        // 1024 chunks of 4 floats
        int key = idx >> 4;
        int pj  = idx & 15;
        int slot = tile * BN + key;
        if (slot < cnt) {
            int src = g_idx[b][slot];
            float4 k4 = *(const float4*)(Kg + (size_t)src * DH + 4 * pj);
            *(uint2*)(dst + key * KSTRW + 2 * pj) =
                make_uint2(h2pk(k4.y, k4.x), h2pk(k4.w, k4.z));
            float4 v4 = *(const float4*)(Vg + (size_t)src * DH + 4 * pj);
            *(uint2*)(dst + TILE_WORDS + key * KSTRW + 2 * pj) =
                make_uint2(h2pk(v4.y, v4.x), h2pk(v4.w, v4.z));
        } else {
            *(uint2*)(dst + key * KSTRW + 2 * pj) = make_uint2(0u, 0u);
            *(uint2*)(dst + TILE_WORDS + key * KSTRW + 2 * pj) = make_uint2(0u, 0u);
        }
    }
}

// ---------------- main attention kernel ----------------
__global__ void __launch_bounds__(128, 4)
attn_mma_kernel(const float* __restrict__ Qg_, float* __restrict__ Og_)
{
    extern __shared__ float sm[];
    const uint32_t sb = smem_u32(sm);

    const int tid  = threadIdx.x;
    const int wid  = tid >> 5;
    const int lane = tid & 31;
    const int r    = lane >> 2;
    const int c    = lane & 3;

    const int bh = blockIdx.y;
    const int b  = bh >> 3;
    const int q0 = blockIdx.x * BM;

    const float* Qg = Qg_ + ((size_t)bh * SEQ + q0 + wid * 16) * DH;
    float* Og = Og_ + ((size_t)bh * SEQ + q0 + wid * 16) * DH;
    const uint32_t* kv = &g_kv[bh][0][0];

    const int cnt   = g_cnt[b];
    const int ntile = (cnt + BN - 1) >> 6;

    const uint32_t lkS = (uint32_t)(((lane >> 4) << 3) + (lane & 7));
    const uint32_t lwS = (uint32_t)(((lane >> 3) & 1) * 4);
    const uint32_t offS = (lkS * KSTRW + lwS) * 4;
    const uint32_t keylP = (uint32_t)((((lane >> 3) & 1) << 3) + (lane & 7));
    const uint32_t dwlP  = (uint32_t)(((lane >> 4) & 1) * 4);
    const uint32_t offP = (keylP * KSTRW + dwlP) * 4;

    // ---- prologue: stage tile 0 ----
    {
        const uint32_t* src = kv;
        #pragma unroll
        for (int i = 0; i < 9; i++) {
            int idx = tid + i * 128;
            cpa16(sb + (uint32_t)idx * 16u, src + idx * 4);
        }
        CP_COMMIT();
    }

    // ---- Q fragments: pre-scaled, single fp16 ----
    uint32_t qh[4][4];
    #pragma unroll
    for (int kt = 0; kt < 4; kt++) {
        #pragma unroll
        for (int rh = 0; rh < 2; rh++) {
            #pragma unroll
            for (int ch = 0; ch < 2; ch++) {
                int row = r + rh * 8;
                int col = kt * 16 + 2 * c + ch * 8;
                float2 v = *(const float2*)(Qg + row * DH + col);
                qh[kt][rh + 2 * ch] = h2pk(v.y * QSCALE, v.x * QSCALE);
            }
        }
    }

    float o[8][4];
    #pragma unroll
    for (int nt = 0; nt < 8; nt++)
        #pragma unroll
        for (int j = 0; j < 4; j++) o[nt][j] = 0.f;
    float lsum0 = 0.f, lsum1 = 0.f;

    #pragma unroll 1
    for (int t = 0; t < ntile; t++) {
        const int buf = t & 1;
        const uint32_t bufb = sb + (buf ? (uint32_t)(BLK_WORDS * 4) : 0u);

        CP_WAIT0();
        __syncthreads();

        // ---- stage tile t+1 ----
        if (t + 1 < ntile) {
            const uint32_t* src = kv + (size_t)(t + 1) * BLK_WORDS;
            const uint32_t dstb = sb + (((t + 1) & 1) ? (uint32_t)(BLK_WORDS * 4) : 0u);
            #pragma unroll
            for (int i = 0; i < 9; i++) {
                int idx = tid + i * 128;
                cpa16(dstb + (uint32_t)idx * 16u, src + idx * 4);
            }
            CP_COMMIT();
        }

        // ---- S = Q*K (single fp16 product) ----
        float s[8][4];
        #pragma unroll
        for (int kt = 0; kt < 4; kt++) {
            #pragma unroll
            for (int np = 0; np < 4; np++) {
                uint32_t adrH = bufb + offS + (uint32_t)(np * 2304 + kt * 32);
                uint32_t bh0, bh1, bh2, bh3;
                LDSM_X4(bh0, bh1, bh2, bh3, adrH);
                if (kt == 0) {
                    mma_f16_z(s[2*np],   qh[0], bh0, bh1);
                    mma_f16_z(s[2*np+1], qh[0], bh2, bh3);
                } else {
                    mma_f16(s[2*np],   qh[kt], bh0, bh1);
                    mma_f16(s[2*np+1], qh[kt], bh2, bh3);
                }
            }
        }

        // ---- softmax + PV interleaved per kt-pair ----
        const bool lastt = (t == ntile - 1);
        const int base = t * BN + 2 * c;
        #pragma unroll
        for (int kt = 0; kt < 4; kt++) {
            uint32_t a[4];
            #pragma unroll
            for (int h = 0; h < 2; h++) {
                const int nt = 2 * kt + h;
                float pv[4];
                #pragma unroll
                for (int j = 0; j < 4; j++) {
                    float u  = ex2f(s[nt][j]);
                    float rr = rcpf(1.f + u);
                    pv[j] = ex2f(rr * -28.853900817779268f);
                }
                if (lastt) {
                    int c0 = base + nt * 8;
                    #pragma unroll
                    for (int j = 0; j < 4; j++)
                        if (c0 + (j & 1) >= cnt) pv[j] = 0.f;
                }
                lsum0 += pv[0] + pv[1];
                lsum1 += pv[2] + pv[3];
                a[2*h]   = h2pk(pv[1], pv[0]);
                a[2*h+1] = h2pk(pv[3], pv[2]);
            }
            #pragma unroll
            for (int np = 0; np < 4; np++) {
                uint32_t adrV = bufb + (uint32_t)(TILE_WORDS * 4) + offP +
                                (uint32_t)(kt * 2304 + np * 32);
                uint32_t v0, v1, v2, v3;
                LDSM_X4_T(v0, v1, v2, v3, adrV);
                mma_f16(o[2*np],   a, v0, v1);
                mma_f16(o[2*np+1], a, v2, v3);
            }
        }
    }

    // ---- quad reduce, normalize, store ----
    lsum0 += __shfl_xor_sync(0xffffffffu, lsum0, 1);
    lsum0 += __shfl_xor_sync(0xffffffffu, lsum0, 2);
    lsum1 += __shfl_xor_sync(0xffffffffu, lsum1, 1);
    lsum1 += __shfl_xor_sync(0xffffffffu, lsum1, 2);
    float inv0 = rcpf(lsum0);
    float inv1 = rcpf(lsum1);
    #pragma unroll
    for (int nt = 0; nt < 8; nt++) {
        int col = nt * 8 + 2 * c;
        *(float2*)(Og + r * DH + col)       = make_float2(o[nt][0] * inv0, o[nt][1] * inv0);
        *(float2*)(Og + (r + 8) * DH + col) = make_float2(o[nt][2] * inv1, o[nt][3] * inv1);
    }
}

extern "C" void kernel_launch(void* const* d_in, const int* in_sizes, int n_in,
                              void* d_out, int out_size)
{
    const float* Q = (const float*)d_in[0];
    const float* K = (const float*)d_in[1];
    const float* V = (const float*)d_in[2];
    const int* mask = (const int*)d_in[3];
    float* out = (float*)d_out;

    cudaFuncSetAttribute(attn_mma_kernel,
                         cudaFuncAttributeMaxDynamicSharedMemorySize, SMEM_BYTES);

    compact_kernel<<<BATCH, 1024>>>(mask);

    dim3 ggrid(MAXTILES, BATCH * HEADS);
    gather_kernel<<<ggrid, 256>>>(K, V);

    dim3 grid(SEQ / BM, BATCH * HEADS);
    attn_mma_kernel<<<grid, 128, SMEM_BYTES>>>(Q, out);
}